// round 8
// baseline (speedup 1.0000x reference)
#include <cuda_runtime.h>
#include <cuda_bf16.h>
#include <cstdint>
#include <cstddef>

#define SEQ 1024
#define BATCH 256
#define IN_DIM 131
#define HID 256
#define OUT_DIM 131
#define T_STEPS 1023
#define MROWS (T_STEPS*BATCH)   // 261888 = 128 * 2046
#define KP_IN 192               // padded K for IN_DIM=131 GEMMs
#define WPAD 260                // padded fp32 row stride for Whh in SMEM

// -------------------- scratch (static device arrays; no allocs) --------------------
__device__ float          g_Zenc[(size_t)MROWS*HID];
__device__ float          g_Zdec[(size_t)MROWS*HID];
__device__ __nv_bfloat16  g_Hhi[(size_t)MROWS*HID];
__device__ __nv_bfloat16  g_Hlo[(size_t)MROWS*HID];
__device__ __nv_bfloat16  g_Xhi[(size_t)MROWS*KP_IN];
__device__ __nv_bfloat16  g_Xlo[(size_t)MROWS*KP_IN];
__device__ __nv_bfloat16  g_Dhi[(size_t)MROWS*KP_IN];
__device__ __nv_bfloat16  g_Dlo[(size_t)MROWS*KP_IN];
__device__ __nv_bfloat16  g_Wh[5*256*256];
__device__ __nv_bfloat16  g_Wl[5*256*256];
__device__ float          g_hn0[BATCH*HID];
__device__ float          g_hn1[BATCH*HID];

// -------------------- common helpers --------------------
__device__ __forceinline__ uint32_t smem_u32(const void* p) {
    return (uint32_t)__cvta_generic_to_shared(p);
}
__device__ __forceinline__ uint32_t my_ctarank() {
    uint32_t r; asm("mov.u32 %0, %%cluster_ctarank;" : "=r"(r)); return r;
}
__device__ __forceinline__ void cluster_sync_() {
    asm volatile("barrier.cluster.arrive.aligned;\n\t"
                 "barrier.cluster.wait.aligned;" ::: "memory");
}
__device__ __forceinline__ uint32_t mapa_u32(uint32_t laddr, uint32_t peer) {
    uint32_t raddr;
    asm volatile("mapa.shared::cluster.u32 %0, %1, %2;" : "=r"(raddr) : "r"(laddr), "r"(peer));
    return raddr;
}
__device__ __forceinline__ void st_cluster_f32(uint32_t raddr, float v) {
    asm volatile("st.shared::cluster.f32 [%0], %1;" :: "r"(raddr), "f"(v) : "memory");
}
__device__ __forceinline__ void mbar_init(uint32_t addr, uint32_t count) {
    asm volatile("mbarrier.init.shared.b64 [%0], %1;" :: "r"(addr), "r"(count) : "memory");
}
__device__ __forceinline__ void mbar_arrive_local(uint32_t addr) {
    asm volatile("mbarrier.arrive.shared.b64 _, [%0];" :: "r"(addr) : "memory");
}
__device__ __forceinline__ void mbar_arrive_remote_addr(uint32_t raddr) {
    asm volatile("mbarrier.arrive.release.cluster.shared::cluster.b64 _, [%0];"
                 :: "r"(raddr) : "memory");
}
__device__ __forceinline__ void mbar_wait_cluster(uint32_t addr, uint32_t parity) {
    asm volatile(
        "{\n\t.reg .pred P;\n\t"
        "WAIT_%=:\n\t"
        "mbarrier.try_wait.parity.acquire.cluster.shared::cta.b64 P, [%0], %1, 0x989680;\n\t"
        "@P bra.uni DONE_%=;\n\t"
        "bra.uni WAIT_%=;\n\t"
        "DONE_%=:\n\t}" :: "r"(addr), "r"(parity) : "memory");
}

// -------------------- mma.sync / ldmatrix primitives (compute_103-legal) --------------------
__device__ __forceinline__ uint32_t swz128(uint32_t off) {
    return off ^ ((off >> 3) & 0x70);
}
__device__ __forceinline__ void ldm4(uint32_t* r, uint32_t addr) {
    asm volatile("ldmatrix.sync.aligned.m8n8.x4.shared.b16 {%0,%1,%2,%3}, [%4];"
        : "=r"(r[0]), "=r"(r[1]), "=r"(r[2]), "=r"(r[3]) : "r"(addr));
}
__device__ __forceinline__ void mma16816(float* d, const uint32_t* a, uint32_t b0, uint32_t b1) {
    asm volatile("mma.sync.aligned.m16n8k16.row.col.f32.bf16.bf16.f32 "
        "{%0,%1,%2,%3}, {%4,%5,%6,%7}, {%8,%9}, {%0,%1,%2,%3};"
        : "+f"(d[0]), "+f"(d[1]), "+f"(d[2]), "+f"(d[3])
        : "r"(a[0]), "r"(a[1]), "r"(a[2]), "r"(a[3]), "r"(b0), "r"(b1));
}

// -------------------- tensor GEMM: C = [Ahi|Alo|Ahi] @ [Bhi|Bhi|Blo]^T + bias --------------------
#define GM_SMEM (2*16384*2)     // 65536: [buf][A 16KB | B 16KB]

__global__ void __launch_bounds__(256,1)
gemm_mma(const __nv_bfloat16* __restrict__ Ahi, const __nv_bfloat16* __restrict__ Alo,
         const __nv_bfloat16* __restrict__ Bhi, const __nv_bfloat16* __restrict__ Blo,
         const float* __restrict__ b1, const float* __restrict__ b2,
         float* __restrict__ C, int Nout, int Kp)
{
    extern __shared__ char smem[];
    const uint32_t sb = smem_u32(smem);
    const int tid = threadIdx.x;
    const int lane = tid & 31, warp = tid >> 5;
    const int wm = warp & 3, wn = warp >> 2;
    const int m0 = blockIdx.x * 128;
    const int n0 = blockIdx.y * 128;

    const int kchunks = Kp >> 6;
    const int nch = 3 * kchunks;

    int lrow[4], lcol[4];
    #pragma unroll
    for (int i = 0; i < 4; i++) {
        int lin = tid + i*256;
        lrow[i] = lin >> 3;
        lcol[i] = (lin & 7) * 16;
    }

    const int aidx = lane & 7;
    uint32_t aoff[2];
    #pragma unroll
    for (int mi = 0; mi < 2; mi++) {
        int r = wm*32 + mi*16 + aidx + ((lane >> 3) & 1)*8;
        aoff[mi] = (uint32_t)(r*128 + ((lane >> 4) & 1)*16);
    }
    uint32_t boff[4];
    #pragma unroll
    for (int j = 0; j < 4; j++) {
        int r = wn*64 + j*16 + aidx + ((lane >> 4) & 1)*8;
        boff[j] = (uint32_t)(r*128 + ((lane >> 3) & 1)*16);
    }

    float acc[2][8][4];
    #pragma unroll
    for (int mi = 0; mi < 2; mi++)
        #pragma unroll
        for (int ni = 0; ni < 8; ni++)
            #pragma unroll
            for (int q = 0; q < 4; q++) acc[mi][ni][q] = 0.f;

    uint4 ra[4], rb[4];
    auto srcA = [&](int c) -> const __nv_bfloat16* {
        int pass = c / kchunks; return (pass == 1) ? Alo : Ahi;
    };
    auto srcB = [&](int c) -> const __nv_bfloat16* {
        int pass = c / kchunks; return (pass == 2) ? Blo : Bhi;
    };
    auto kcOf = [&](int c) -> int { int pass = c / kchunks; return c - pass*kchunks; };

    {
        const __nv_bfloat16* Ap = srcA(0);
        const __nv_bfloat16* Bp = srcB(0);
        #pragma unroll
        for (int i = 0; i < 4; i++) {
            ra[i] = *(const uint4*)((const char*)Ap + ((size_t)(m0 + lrow[i])*Kp)*2 + lcol[i]);
            rb[i] = *(const uint4*)((const char*)Bp + ((size_t)(n0 + lrow[i])*Kp)*2 + lcol[i]);
        }
        #pragma unroll
        for (int i = 0; i < 4; i++) {
            *(uint4*)(smem + swz128((uint32_t)(lrow[i]*128 + lcol[i]))) = ra[i];
            *(uint4*)(smem + 16384 + swz128((uint32_t)(lrow[i]*128 + lcol[i]))) = rb[i];
        }
    }
    __syncthreads();

    for (int c = 0; c < nch; ++c) {
        const int buf = c & 1;
        const uint32_t aB = sb + buf*32768;
        const uint32_t bB = sb + buf*32768 + 16384;

        if (c + 1 < nch) {
            const __nv_bfloat16* Ap = srcA(c+1);
            const __nv_bfloat16* Bp = srcB(c+1);
            const int kc = kcOf(c+1);
            #pragma unroll
            for (int i = 0; i < 4; i++) {
                ra[i] = *(const uint4*)((const char*)Ap + ((size_t)(m0 + lrow[i])*Kp)*2 + kc*128 + lcol[i]);
                rb[i] = *(const uint4*)((const char*)Bp + ((size_t)(n0 + lrow[i])*Kp)*2 + kc*128 + lcol[i]);
            }
        }

        #pragma unroll
        for (int ks = 0; ks < 4; ks++) {
            uint32_t afr[2][4];
            #pragma unroll
            for (int mi = 0; mi < 2; mi++)
                ldm4(afr[mi], aB + swz128(aoff[mi] + ks*32));
            #pragma unroll
            for (int j = 0; j < 4; j++) {
                uint32_t bfr[4];
                ldm4(bfr, bB + swz128(boff[j] + ks*32));
                #pragma unroll
                for (int mi = 0; mi < 2; mi++) {
                    mma16816(acc[mi][2*j],   afr[mi], bfr[0], bfr[1]);
                    mma16816(acc[mi][2*j+1], afr[mi], bfr[2], bfr[3]);
                }
            }
        }

        if (c + 1 < nch) {
            char* ag = smem + (buf ^ 1)*32768;
            char* bg = smem + (buf ^ 1)*32768 + 16384;
            #pragma unroll
            for (int i = 0; i < 4; i++) {
                *(uint4*)(ag + swz128((uint32_t)(lrow[i]*128 + lcol[i]))) = ra[i];
                *(uint4*)(bg + swz128((uint32_t)(lrow[i]*128 + lcol[i]))) = rb[i];
            }
        }
        __syncthreads();
    }

    const int er = lane >> 2, ec = (lane & 3) * 2;
    #pragma unroll
    for (int mi = 0; mi < 2; mi++) {
        #pragma unroll
        for (int ni = 0; ni < 8; ni++) {
            const int nbase = n0 + wn*64 + ni*8 + ec;
            const int mbase = m0 + wm*32 + mi*16 + er;
            #pragma unroll
            for (int half = 0; half < 2; half++) {
                int m = mbase + half*8;
                #pragma unroll
                for (int q = 0; q < 2; q++) {
                    int n = nbase + q;
                    if (n < Nout) {
                        float bias = __ldg(&b1[n]) + (b2 ? __ldg(&b2[n]) : 0.f);
                        C[(size_t)m*Nout + n] = acc[mi][ni][half*2 + q] + bias;
                    }
                }
            }
        }
    }
}

// -------------------- recurrence: h_t = tanh(Z_t + h_{t-1} @ Whh^T) --------------------
// 2-CTA cluster; each CTA holds 128 j-rows of Whh in SMEM as sW[j][k] (stride WPAD).
// 512 threads (4 warps/SMSP): thread = (ks = tid>>7 k-slice of 64, jp = tid&127 one j).
// Unified per-step mbarrier (512 local + 512 remote arrivals).
struct RArgs {
    const float*   Z;
    __nv_bfloat16* outHi;
    __nv_bfloat16* outLo;
    const float*   W;
    const float*   hInit;
    float*         hFinal;
};

#define RTHREADS 512
#define RECUR_SMEM(RBB) ((4 + 128*WPAD + 2*(RBB)*HID + 4*(RBB)*128)*4)

template<int RBB>
__global__ void __launch_bounds__(RTHREADS,1) __cluster_dims__(2,1,1)
recur_kernel(RArgs a0, RArgs a1, int nClustA)
{
    extern __shared__ float smemf[];
    float* sW = smemf + 4;                 // [128][WPAD]
    float* sH = sW + 128*WPAD;             // 2 * RBB * 256 (double buffer)
    float* sP = sH + 2*RBB*HID;            // [4][RBB][128] partials

    const int tid = threadIdx.x;
    const uint32_t rank = my_ctarank();
    const uint32_t peer = rank ^ 1u;
    const int cid = (int)(blockIdx.x >> 1);
    const bool isA = (cid < nClustA);
    RArgs A = isA ? a0 : a1;
    const int batch0 = (isA ? cid : (cid - nClustA)) * RBB;
    const uint32_t barAddr = smem_u32(smemf);

    if (tid == 0) mbar_init(barAddr, 2*RTHREADS);

    // W rows copied straight (no transpose): sW[j*WPAD + k] = W[(rank*128+j)*HID + k]
    for (int idx = tid; idx < 128*HID; idx += RTHREADS) {
        int j = idx >> 8;
        int k = idx & 255;
        sW[j*WPAD + k] = A.W[((size_t)(rank*128 + j))*HID + k];
    }
    for (int idx = tid; idx < RBB*HID; idx += RTHREADS)
        sH[idx] = A.hInit ? A.hInit[(size_t)batch0*HID + idx] : 0.f;

    // loop-invariant epilogue addresses
    constexpr int NOUT = (RBB*128)/RTHREADS;   // 1 (RBB=4) or 2 (RBB=8)
    const uint32_t rBar = mapa_u32(barAddr, peer);
    uint32_t rHn[2][NOUT];
    float*   lHn[2][NOUT];
    int      bOf[NOUT], jOf[NOUT];
    #pragma unroll
    for (int i = 0; i < NOUT; i++) {
        int o = tid + i*RTHREADS;
        int b = o >> 7, jj = o & 127;
        bOf[i] = b; jOf[i] = jj;
        #pragma unroll
        for (int buf = 0; buf < 2; buf++) {
            float* dst = sH + buf*RBB*HID + b*HID + (int)rank*128 + jj;
            lHn[buf][i] = dst;
            rHn[buf][i] = mapa_u32(smem_u32(dst), peer);
        }
    }

    __syncthreads();
    cluster_sync_();

    const int jp = tid & 127;
    const int ks = tid >> 7;
    const int kbase = ks*64;
    const float* wRow = sW + jp*WPAD;

    for (int t = 0; t < T_STEPS; ++t) {
        const float* hc = sH + (t & 1)*RBB*HID;
        const int nbuf = (t + 1) & 1;

        // epilogue Z prefetch
        float zreg[NOUT];
        const float* Zt = A.Z + ((size_t)t*BATCH + batch0)*HID;
        #pragma unroll
        for (int i = 0; i < NOUT; i++)
            zreg[i] = Zt[bOf[i]*HID + (int)rank*128 + jOf[i]];

        float acc[RBB];
        #pragma unroll
        for (int b = 0; b < RBB; b++) acc[b] = 0.f;

        #pragma unroll 4
        for (int k4 = kbase; k4 < kbase + 64; k4 += 4) {
            float4 w = *(const float4*)&wRow[k4];       // conflict-free (WPAD)
            #pragma unroll
            for (int b = 0; b < RBB; b++) {
                float4 hv = *(const float4*)&hc[b*HID + k4];  // warp-broadcast
                acc[b] = fmaf(w.x, hv.x, acc[b]);
                acc[b] = fmaf(w.y, hv.y, acc[b]);
                acc[b] = fmaf(w.z, hv.z, acc[b]);
                acc[b] = fmaf(w.w, hv.w, acc[b]);
            }
        }
        #pragma unroll
        for (int b = 0; b < RBB; b++)
            sP[(ks*RBB + b)*128 + jp] = acc[b];
        __syncthreads();

        // epilogue: reduce 4 slice-partials, add Z, tanh, publish local+remote
        #pragma unroll
        for (int i = 0; i < NOUT; i++) {
            float s = zreg[i];
            #pragma unroll
            for (int p = 0; p < 4; p++)
                s += sP[(p*RBB + bOf[i])*128 + jOf[i]];
            float y = tanhf(s);
            *lHn[nbuf][i] = y;
            st_cluster_f32(rHn[nbuf][i], y);
            if (A.outHi) {
                size_t gi = ((size_t)t*BATCH + batch0 + bOf[i])*HID + (int)rank*128 + jOf[i];
                __nv_bfloat16 h = __float2bfloat16(y);
                A.outHi[gi] = h;
                A.outLo[gi] = __float2bfloat16(y - __bfloat162float(h));
            }
            if (A.hFinal && t == T_STEPS-1)
                A.hFinal[(size_t)(batch0 + bOf[i])*HID + (int)rank*128 + jOf[i]] = y;
        }
        // arrivals double as read-certificates for hc (WAR-safe vs peer's next write)
        mbar_arrive_remote_addr(rBar);
        mbar_arrive_local(barAddr);
        mbar_wait_cluster(barAddr, (uint32_t)(t & 1));
    }
    cluster_sync_();
}

// -------------------- split converters --------------------
__global__ void wsplit(const float* __restrict__ W, __nv_bfloat16* __restrict__ hi,
                       __nv_bfloat16* __restrict__ lo, int Nw, int Kw, int Kp)
{
    int i = blockIdx.x*blockDim.x + threadIdx.x;
    if (i >= 256*Kp) return;
    int r = i / Kp, c = i - r*Kp;
    float v = (r < Nw && c < Kw) ? W[r*Kw + c] : 0.f;
    __nv_bfloat16 h = __float2bfloat16(v);
    hi[i] = h;
    lo[i] = __float2bfloat16(v - __bfloat162float(h));
}

__global__ void xsplit(const float* __restrict__ src, __nv_bfloat16* __restrict__ hi,
                       __nv_bfloat16* __restrict__ lo)
{
    const size_t total = (size_t)MROWS*KP_IN;
    for (size_t i = (size_t)blockIdx.x*blockDim.x + threadIdx.x; i < total;
         i += (size_t)gridDim.x*blockDim.x) {
        size_t r = i / KP_IN;
        int c = (int)(i - r*KP_IN);
        float v = (c < IN_DIM) ? src[r*IN_DIM + c] : 0.f;
        __nv_bfloat16 h = __float2bfloat16(v);
        hi[i] = h;
        lo[i] = __float2bfloat16(v - __bfloat162float(h));
    }
}

__global__ void decsplit(const float* __restrict__ X, const float* __restrict__ Y,
                         __nv_bfloat16* __restrict__ hi, __nv_bfloat16* __restrict__ lo)
{
    const size_t total = (size_t)MROWS*KP_IN;
    for (size_t i = (size_t)blockIdx.x*blockDim.x + threadIdx.x; i < total;
         i += (size_t)gridDim.x*blockDim.x) {
        size_t r = i / KP_IN;
        int c = (int)(i - r*KP_IN);
        float v = 0.f;
        if (c < IN_DIM)
            v = (r < BATCH) ? X[((size_t)1023*BATCH + r)*IN_DIM + c]
                            : Y[(r - BATCH)*IN_DIM + c];
        __nv_bfloat16 h = __float2bfloat16(v);
        hi[i] = h;
        lo[i] = __float2bfloat16(v - __bfloat162float(h));
    }
}

// -------------------- log_softmax in place --------------------
__global__ void __launch_bounds__(256) logsoftmax_kernel(float* __restrict__ out, int rows) {
    int row = blockIdx.x*8 + (threadIdx.x >> 5);
    int lane = threadIdx.x & 31;
    if (row >= rows) return;
    float* p = out + (size_t)row*OUT_DIM;
    float v[5];
    float mx = -1e30f;
    #pragma unroll
    for (int i = 0; i < 5; i++) {
        int idx = lane + i*32;
        v[i] = (idx < OUT_DIM) ? p[idx] : -1e30f;
        mx = fmaxf(mx, v[i]);
    }
    #pragma unroll
    for (int o = 16; o > 0; o >>= 1)
        mx = fmaxf(mx, __shfl_xor_sync(0xffffffffu, mx, o));
    float s = 0.f;
    #pragma unroll
    for (int i = 0; i < 5; i++) {
        int idx = lane + i*32;
        if (idx < OUT_DIM) s += expf(v[i] - mx);
    }
    #pragma unroll
    for (int o = 16; o > 0; o >>= 1)
        s += __shfl_xor_sync(0xffffffffu, s, o);
    float lse = mx + logf(s);
    #pragma unroll
    for (int i = 0; i < 5; i++) {
        int idx = lane + i*32;
        if (idx < OUT_DIM) p[idx] = v[i] - lse;
    }
}

// -------------------- driver --------------------
extern "C" void kernel_launch(void* const* d_in, const int* in_sizes, int n_in,
                              void* d_out, int out_size) {
    const float* X     = (const float*)d_in[0];
    const float* Y     = (const float*)d_in[1];
    const float* eWih0 = (const float*)d_in[2];
    const float* eWhh0 = (const float*)d_in[3];
    const float* ebih0 = (const float*)d_in[4];
    const float* ebhh0 = (const float*)d_in[5];
    const float* eWih1 = (const float*)d_in[6];
    const float* eWhh1 = (const float*)d_in[7];
    const float* ebih1 = (const float*)d_in[8];
    const float* ebhh1 = (const float*)d_in[9];
    const float* dWih0 = (const float*)d_in[10];
    const float* dWhh0 = (const float*)d_in[11];
    const float* dbih0 = (const float*)d_in[12];
    const float* dbhh0 = (const float*)d_in[13];
    const float* dWih1 = (const float*)d_in[14];
    const float* dWhh1 = (const float*)d_in[15];
    const float* dbih1 = (const float*)d_in[16];
    const float* dbhh1 = (const float*)d_in[17];
    const float* lin_W = (const float*)d_in[18];
    const float* lin_b = (const float*)d_in[19];
    float* out = (float*)d_out;

    float *Zenc, *Zdec, *hn0, *hn1;
    __nv_bfloat16 *Hhi, *Hlo, *Xhi, *Xlo, *Dhi, *Dlo, *Wh, *Wl;
    cudaGetSymbolAddress((void**)&Zenc, g_Zenc);
    cudaGetSymbolAddress((void**)&Zdec, g_Zdec);
    cudaGetSymbolAddress((void**)&Hhi,  g_Hhi);
    cudaGetSymbolAddress((void**)&Hlo,  g_Hlo);
    cudaGetSymbolAddress((void**)&Xhi,  g_Xhi);
    cudaGetSymbolAddress((void**)&Xlo,  g_Xlo);
    cudaGetSymbolAddress((void**)&Dhi,  g_Dhi);
    cudaGetSymbolAddress((void**)&Dlo,  g_Dlo);
    cudaGetSymbolAddress((void**)&Wh,   g_Wh);
    cudaGetSymbolAddress((void**)&Wl,   g_Wl);
    cudaGetSymbolAddress((void**)&hn0,  g_hn0);
    cudaGetSymbolAddress((void**)&hn1,  g_hn1);

    cudaFuncSetAttribute((const void*)recur_kernel<4>,
                         cudaFuncAttributeMaxDynamicSharedMemorySize, RECUR_SMEM(4));
    cudaFuncSetAttribute((const void*)recur_kernel<8>,
                         cudaFuncAttributeMaxDynamicSharedMemorySize, RECUR_SMEM(8));
    cudaFuncSetAttribute((const void*)gemm_mma,
                         cudaFuncAttributeMaxDynamicSharedMemorySize, GM_SMEM);

    const int WSTRIDE = 256*256;
    const dim3 gG(MROWS/128, 2);

    wsplit<<<(256*KP_IN+255)/256, 256>>>(eWih0, Wh+0*WSTRIDE, Wl+0*WSTRIDE, HID, IN_DIM, KP_IN);
    wsplit<<<(256*KP_IN+255)/256, 256>>>(dWih0, Wh+1*WSTRIDE, Wl+1*WSTRIDE, HID, IN_DIM, KP_IN);
    wsplit<<<(256*256+255)/256, 256>>>(eWih1, Wh+2*WSTRIDE, Wl+2*WSTRIDE, HID, HID, 256);
    wsplit<<<(256*256+255)/256, 256>>>(dWih1, Wh+3*WSTRIDE, Wl+3*WSTRIDE, HID, HID, 256);
    wsplit<<<(256*256+255)/256, 256>>>(lin_W, Wh+4*WSTRIDE, Wl+4*WSTRIDE, OUT_DIM, HID, 256);
    xsplit<<<4096, 256>>>(X, Xhi, Xlo);
    decsplit<<<4096, 256>>>(X, Y, Dhi, Dlo);

    gemm_mma<<<gG, 256, GM_SMEM>>>(Xhi, Xlo, Wh+0*WSTRIDE, Wl+0*WSTRIDE,
                                   ebih0, ebhh0, Zenc, 256, KP_IN);
    gemm_mma<<<gG, 256, GM_SMEM>>>(Dhi, Dlo, Wh+1*WSTRIDE, Wl+1*WSTRIDE,
                                   dbih0, dbhh0, Zdec, 256, KP_IN);
    {
        RArgs a; a.Z = Zenc; a.outHi = Hhi; a.outLo = Hlo; a.W = eWhh0; a.hInit = nullptr; a.hFinal = hn0;
        recur_kernel<4><<<128, RTHREADS, RECUR_SMEM(4)>>>(a, a, 64);
    }
    gemm_mma<<<gG, 256, GM_SMEM>>>(Hhi, Hlo, Wh+2*WSTRIDE, Wl+2*WSTRIDE,
                                   ebih1, ebhh1, Zenc, 256, 256);
    {
        RArgs a0; a0.Z = Zenc; a0.outHi = nullptr; a0.outLo = nullptr; a0.W = eWhh1; a0.hInit = nullptr; a0.hFinal = hn1;
        RArgs a1; a1.Z = Zdec; a1.outHi = Hhi;     a1.outLo = Hlo;     a1.W = dWhh0; a1.hInit = hn0;     a1.hFinal = nullptr;
        recur_kernel<8><<<128, RTHREADS, RECUR_SMEM(8)>>>(a0, a1, 32);
    }
    gemm_mma<<<gG, 256, GM_SMEM>>>(Hhi, Hlo, Wh+3*WSTRIDE, Wl+3*WSTRIDE,
                                   dbih1, dbhh1, Zdec, 256, 256);
    {
        RArgs a; a.Z = Zdec; a.outHi = Hhi; a.outLo = Hlo; a.W = dWhh1; a.hInit = hn1; a.hFinal = nullptr;
        recur_kernel<4><<<128, RTHREADS, RECUR_SMEM(4)>>>(a, a, 64);
    }
    gemm_mma<<<gG, 256, GM_SMEM>>>(Hhi, Hlo, Wh+4*WSTRIDE, Wl+4*WSTRIDE,
                                   lin_b, nullptr, out, OUT_DIM, 256);
    logsoftmax_kernel<<<(MROWS + 7)/8, 256>>>(out, MROWS);
}

// round 9
// speedup vs baseline: 1.0019x; 1.0019x over previous
#include <cuda_runtime.h>
#include <cuda_bf16.h>
#include <cstdint>
#include <cstddef>

#define SEQ 1024
#define BATCH 256
#define IN_DIM 131
#define HID 256
#define OUT_DIM 131
#define T_STEPS 1023
#define MROWS (T_STEPS*BATCH)   // 261888 = 128 * 2046
#define KP_IN 192               // padded K for IN_DIM=131 GEMMs

// -------------------- scratch (static device arrays; no allocs) --------------------
__device__ float          g_Zenc[(size_t)MROWS*HID];
__device__ float          g_Zdec[(size_t)MROWS*HID];
__device__ __nv_bfloat16  g_Hhi[(size_t)MROWS*HID];
__device__ __nv_bfloat16  g_Hlo[(size_t)MROWS*HID];
__device__ __nv_bfloat16  g_Xhi[(size_t)MROWS*KP_IN];
__device__ __nv_bfloat16  g_Xlo[(size_t)MROWS*KP_IN];
__device__ __nv_bfloat16  g_Dhi[(size_t)MROWS*KP_IN];
__device__ __nv_bfloat16  g_Dlo[(size_t)MROWS*KP_IN];
__device__ __nv_bfloat16  g_Wh[5*256*256];
__device__ __nv_bfloat16  g_Wl[5*256*256];
__device__ float          g_hn0[BATCH*HID];
__device__ float          g_hn1[BATCH*HID];

// -------------------- common helpers --------------------
__device__ __forceinline__ uint32_t smem_u32(const void* p) {
    return (uint32_t)__cvta_generic_to_shared(p);
}
__device__ __forceinline__ uint32_t my_ctarank() {
    uint32_t r; asm("mov.u32 %0, %%cluster_ctarank;" : "=r"(r)); return r;
}
__device__ __forceinline__ void cluster_sync_() {
    asm volatile("barrier.cluster.arrive.aligned;\n\t"
                 "barrier.cluster.wait.aligned;" ::: "memory");
}
__device__ __forceinline__ uint32_t mapa_u32(uint32_t laddr, uint32_t peer) {
    uint32_t raddr;
    asm volatile("mapa.shared::cluster.u32 %0, %1, %2;" : "=r"(raddr) : "r"(laddr), "r"(peer));
    return raddr;
}
__device__ __forceinline__ void st_cluster_u32(uint32_t raddr, uint32_t v) {
    asm volatile("st.shared::cluster.u32 [%0], %1;" :: "r"(raddr), "r"(v) : "memory");
}
__device__ __forceinline__ void sts_u32(uint32_t addr, uint32_t v) {
    asm volatile("st.shared.b32 [%0], %1;" :: "r"(addr), "r"(v) : "memory");
}
__device__ __forceinline__ void mbar_init(uint32_t addr, uint32_t count) {
    asm volatile("mbarrier.init.shared.b64 [%0], %1;" :: "r"(addr), "r"(count) : "memory");
}
__device__ __forceinline__ void mbar_arrive_local(uint32_t addr) {
    asm volatile("mbarrier.arrive.shared.b64 _, [%0];" :: "r"(addr) : "memory");
}
__device__ __forceinline__ void mbar_arrive_remote_addr(uint32_t raddr) {
    asm volatile("mbarrier.arrive.release.cluster.shared::cluster.b64 _, [%0];"
                 :: "r"(raddr) : "memory");
}
__device__ __forceinline__ void mbar_wait_cluster(uint32_t addr, uint32_t parity) {
    asm volatile(
        "{\n\t.reg .pred P;\n\t"
        "WAIT_%=:\n\t"
        "mbarrier.try_wait.parity.acquire.cluster.shared::cta.b64 P, [%0], %1, 0x989680;\n\t"
        "@P bra.uni DONE_%=;\n\t"
        "bra.uni WAIT_%=;\n\t"
        "DONE_%=:\n\t}" :: "r"(addr), "r"(parity) : "memory");
}
__device__ __forceinline__ float ftanh(float x) {
    float xc = fminf(fmaxf(x, -15.f), 15.f);
    float e = __expf(2.f*xc);
    return __fdividef(e - 1.f, e + 1.f);
}

// -------------------- mma.sync / ldmatrix primitives (compute_103-legal) --------------------
__device__ __forceinline__ uint32_t swz128(uint32_t off) {
    return off ^ ((off >> 3) & 0x70);
}
__device__ __forceinline__ void ldm4(uint32_t* r, uint32_t addr) {
    asm volatile("ldmatrix.sync.aligned.m8n8.x4.shared.b16 {%0,%1,%2,%3}, [%4];"
        : "=r"(r[0]), "=r"(r[1]), "=r"(r[2]), "=r"(r[3]) : "r"(addr));
}
__device__ __forceinline__ void mma16816(float* d, const uint32_t* a, uint32_t b0, uint32_t b1) {
    asm volatile("mma.sync.aligned.m16n8k16.row.col.f32.bf16.bf16.f32 "
        "{%0,%1,%2,%3}, {%4,%5,%6,%7}, {%8,%9}, {%0,%1,%2,%3};"
        : "+f"(d[0]), "+f"(d[1]), "+f"(d[2]), "+f"(d[3])
        : "r"(a[0]), "r"(a[1]), "r"(a[2]), "r"(a[3]), "r"(b0), "r"(b1));
}

// -------------------- tensor GEMM: C = [Ahi|Alo|Ahi] @ [Bhi|Bhi|Blo]^T + bias --------------------
#define GM_SMEM (2*16384*2)     // 65536: [buf][A 16KB | B 16KB]

__global__ void __launch_bounds__(256,1)
gemm_mma(const __nv_bfloat16* __restrict__ Ahi, const __nv_bfloat16* __restrict__ Alo,
         const __nv_bfloat16* __restrict__ Bhi, const __nv_bfloat16* __restrict__ Blo,
         const float* __restrict__ b1, const float* __restrict__ b2,
         float* __restrict__ C, int Nout, int Kp)
{
    extern __shared__ char smem[];
    const uint32_t sb = smem_u32(smem);
    const int tid = threadIdx.x;
    const int lane = tid & 31, warp = tid >> 5;
    const int wm = warp & 3, wn = warp >> 2;
    const int m0 = blockIdx.x * 128;
    const int n0 = blockIdx.y * 128;

    const int kchunks = Kp >> 6;
    const int nch = 3 * kchunks;

    int lrow[4], lcol[4];
    #pragma unroll
    for (int i = 0; i < 4; i++) {
        int lin = tid + i*256;
        lrow[i] = lin >> 3;
        lcol[i] = (lin & 7) * 16;
    }

    const int aidx = lane & 7;
    uint32_t aoff[2];
    #pragma unroll
    for (int mi = 0; mi < 2; mi++) {
        int r = wm*32 + mi*16 + aidx + ((lane >> 3) & 1)*8;
        aoff[mi] = (uint32_t)(r*128 + ((lane >> 4) & 1)*16);
    }
    uint32_t boff[4];
    #pragma unroll
    for (int j = 0; j < 4; j++) {
        int r = wn*64 + j*16 + aidx + ((lane >> 4) & 1)*8;
        boff[j] = (uint32_t)(r*128 + ((lane >> 3) & 1)*16);
    }

    float acc[2][8][4];
    #pragma unroll
    for (int mi = 0; mi < 2; mi++)
        #pragma unroll
        for (int ni = 0; ni < 8; ni++)
            #pragma unroll
            for (int q = 0; q < 4; q++) acc[mi][ni][q] = 0.f;

    uint4 ra[4], rb[4];
    auto srcA = [&](int c) -> const __nv_bfloat16* {
        int pass = c / kchunks; return (pass == 1) ? Alo : Ahi;
    };
    auto srcB = [&](int c) -> const __nv_bfloat16* {
        int pass = c / kchunks; return (pass == 2) ? Blo : Bhi;
    };
    auto kcOf = [&](int c) -> int { int pass = c / kchunks; return c - pass*kchunks; };

    {
        const __nv_bfloat16* Ap = srcA(0);
        const __nv_bfloat16* Bp = srcB(0);
        #pragma unroll
        for (int i = 0; i < 4; i++) {
            ra[i] = *(const uint4*)((const char*)Ap + ((size_t)(m0 + lrow[i])*Kp)*2 + lcol[i]);
            rb[i] = *(const uint4*)((const char*)Bp + ((size_t)(n0 + lrow[i])*Kp)*2 + lcol[i]);
        }
        #pragma unroll
        for (int i = 0; i < 4; i++) {
            *(uint4*)(smem + swz128((uint32_t)(lrow[i]*128 + lcol[i]))) = ra[i];
            *(uint4*)(smem + 16384 + swz128((uint32_t)(lrow[i]*128 + lcol[i]))) = rb[i];
        }
    }
    __syncthreads();

    for (int c = 0; c < nch; ++c) {
        const int buf = c & 1;
        const uint32_t aB = sb + buf*32768;
        const uint32_t bB = sb + buf*32768 + 16384;

        if (c + 1 < nch) {
            const __nv_bfloat16* Ap = srcA(c+1);
            const __nv_bfloat16* Bp = srcB(c+1);
            const int kc = kcOf(c+1);
            #pragma unroll
            for (int i = 0; i < 4; i++) {
                ra[i] = *(const uint4*)((const char*)Ap + ((size_t)(m0 + lrow[i])*Kp)*2 + kc*128 + lcol[i]);
                rb[i] = *(const uint4*)((const char*)Bp + ((size_t)(n0 + lrow[i])*Kp)*2 + kc*128 + lcol[i]);
            }
        }

        #pragma unroll
        for (int ks = 0; ks < 4; ks++) {
            uint32_t afr[2][4];
            #pragma unroll
            for (int mi = 0; mi < 2; mi++)
                ldm4(afr[mi], aB + swz128(aoff[mi] + ks*32));
            #pragma unroll
            for (int j = 0; j < 4; j++) {
                uint32_t bfr[4];
                ldm4(bfr, bB + swz128(boff[j] + ks*32));
                #pragma unroll
                for (int mi = 0; mi < 2; mi++) {
                    mma16816(acc[mi][2*j],   afr[mi], bfr[0], bfr[1]);
                    mma16816(acc[mi][2*j+1], afr[mi], bfr[2], bfr[3]);
                }
            }
        }

        if (c + 1 < nch) {
            char* ag = smem + (buf ^ 1)*32768;
            char* bg = smem + (buf ^ 1)*32768 + 16384;
            #pragma unroll
            for (int i = 0; i < 4; i++) {
                *(uint4*)(ag + swz128((uint32_t)(lrow[i]*128 + lcol[i]))) = ra[i];
                *(uint4*)(bg + swz128((uint32_t)(lrow[i]*128 + lcol[i]))) = rb[i];
            }
        }
        __syncthreads();
    }

    const int er = lane >> 2, ec = (lane & 3) * 2;
    #pragma unroll
    for (int mi = 0; mi < 2; mi++) {
        #pragma unroll
        for (int ni = 0; ni < 8; ni++) {
            const int nbase = n0 + wn*64 + ni*8 + ec;
            const int mbase = m0 + wm*32 + mi*16 + er;
            #pragma unroll
            for (int half = 0; half < 2; half++) {
                int m = mbase + half*8;
                #pragma unroll
                for (int q = 0; q < 2; q++) {
                    int n = nbase + q;
                    if (n < Nout) {
                        float bias = __ldg(&b1[n]) + (b2 ? __ldg(&b2[n]) : 0.f);
                        C[(size_t)m*Nout + n] = acc[mi][ni][half*2 + q] + bias;
                    }
                }
            }
        }
    }
}

// -------------------- tensor-core recurrence: h_t = tanh(Z_t + h_{t-1} @ Whh^T) ----------
// 2-CTA cluster; CTA rank owns j in [128r, 128r+128). RBB=16 batch rows per cluster.
// Per step: M=16, N=128, K=256 GEMM via mma.sync with split-bf16 (3 passes:
// h_hi*W_hi + h_lo*W_hi + h_hi*W_lo). W split once into SMEM; h kept as split-bf16
// chunk images (k64 x 128B, SW128) double-buffered; halves exchanged via DSMEM.
struct RArgs {
    const float*   Z;       // [T, BATCH, HID] fp32, incl. both biases
    __nv_bfloat16* outHi;   // nullable: split-bf16 sequence output
    __nv_bfloat16* outLo;
    const float*   W;       // Whh [HID, HID] fp32
    const float*   hInit;   // nullable -> zeros
    float*         hFinal;  // nullable
};

#define R_M 16
#define R_WHI 1024
#define R_WLO (1024 + 65536)
#define R_H0  (1024 + 131072)
#define R_HBUF(b) (R_H0 + (b)*16384)      // per buf: hi 8KB then lo 8KB
#define R_SMEM_TOTAL (R_H0 + 32768)       // 164864 bytes

__global__ void __launch_bounds__(256,1) __cluster_dims__(2,1,1)
recur_mma(RArgs a0, RArgs a1, int nClustA)
{
    extern __shared__ char smem[];
    const uint32_t sb = smem_u32(smem);
    const int tid = threadIdx.x;
    const int lane = tid & 31, wid = tid >> 5;
    const uint32_t rank = my_ctarank();
    const uint32_t peer = rank ^ 1u;
    const int cid = (int)(blockIdx.x >> 1);
    const bool isA = (cid < nClustA);
    RArgs A = isA ? a0 : a1;
    const int batch0 = (isA ? cid : (cid - nClustA)) * R_M;
    const uint32_t barAddr = sb;

    if (tid == 0) mbar_init(barAddr, 512);

    // Split W into SMEM chunk images: chunk c = k in [64c, 64c+64), 128 n-rows x 128B, SW128.
    for (int idx = tid; idx < 128*HID; idx += 256) {
        int n = idx >> 8, k = idx & 255;
        float v = A.W[((size_t)(rank*128 + n))*HID + k];
        __nv_bfloat16 h = __float2bfloat16(v);
        __nv_bfloat16 l = __float2bfloat16(v - __bfloat162float(h));
        uint32_t off = (uint32_t)((k >> 6)*16384) + swz128((uint32_t)(n*128 + (k & 63)*2));
        *(__nv_bfloat16*)(smem + R_WHI + off) = h;
        *(__nv_bfloat16*)(smem + R_WLO + off) = l;
    }
    // h init (buf 0): full 16x256 split-bf16 replica in both CTAs
    for (int idx = tid; idx < R_M*HID; idx += 256) {
        int m = idx >> 8, k = idx & 255;
        float v = A.hInit ? A.hInit[(size_t)(batch0 + m)*HID + k] : 0.f;
        __nv_bfloat16 h = __float2bfloat16(v);
        __nv_bfloat16 l = __float2bfloat16(v - __bfloat162float(h));
        uint32_t off = (uint32_t)((k >> 6)*2048) + swz128((uint32_t)(m*128 + (k & 63)*2));
        *(__nv_bfloat16*)(smem + R_HBUF(0) + off) = h;
        *(__nv_bfloat16*)(smem + R_HBUF(0) + 8192 + off) = l;
    }

    // fragment offsets (same verified patterns as gemm_mma)
    const int aidx = lane & 7;
    const uint32_t aoff = (uint32_t)((aidx + ((lane >> 3) & 1)*8)*128 + ((lane >> 4) & 1)*16);
    const uint32_t boff = (uint32_t)((wid*16 + aidx + ((lane >> 4) & 1)*8)*128 + ((lane >> 3) & 1)*16);
    const int er = lane >> 2, ec = (lane & 3)*2;
    const uint32_t rBar = mapa_u32(barAddr, peer);

    // epilogue slots: p = half*2 + t8 -> (row m, global col kg, pair)
    int mIdx[4], kgIdx[4];
    uint32_t hOffPair[4];   // offset within an h buffer (hi region)
    #pragma unroll
    for (int p = 0; p < 4; p++) {
        int half = p >> 1, t8 = p & 1;
        int m = er + half*8;
        int kg = (int)rank*128 + wid*16 + t8*8 + ec;
        mIdx[p] = m; kgIdx[p] = kg;
        hOffPair[p] = (uint32_t)((kg >> 6)*2048) + swz128((uint32_t)(m*128 + (kg & 63)*2));
    }

    __syncthreads();
    cluster_sync_();

    for (int t = 0; t < T_STEPS; ++t) {
        const uint32_t hb = sb + R_HBUF(t & 1);
        const uint32_t hn = sb + R_HBUF((t + 1) & 1);

        // Z prefetch (hidden under the matvec)
        const float* Zr = A.Z + ((size_t)t*BATCH + batch0)*HID;
        float2 zv[4];
        #pragma unroll
        for (int p = 0; p < 4; p++)
            zv[p] = *(const float2*)&Zr[mIdx[p]*HID + kgIdx[p]];

        float acc[8];
        #pragma unroll
        for (int i = 0; i < 8; i++) acc[i] = 0.f;

        #pragma unroll
        for (int pass = 0; pass < 3; pass++) {
            const uint32_t aBase = hb + (pass == 1 ? 8192u : 0u);
            const uint32_t wBase = sb + (pass == 2 ? R_WLO : R_WHI);
            #pragma unroll
            for (int ch = 0; ch < 4; ch++) {
                const uint32_t aT = aBase + ch*2048;
                const uint32_t bT = wBase + ch*16384;
                #pragma unroll
                for (int ks = 0; ks < 4; ks++) {
                    uint32_t af[4], bf[4];
                    ldm4(af, aT + swz128(aoff + ks*32));
                    ldm4(bf, bT + swz128(boff + ks*32));
                    mma16816(acc + 0, af, bf[0], bf[1]);
                    mma16816(acc + 4, af, bf[2], bf[3]);
                }
            }
        }

        // epilogue: add Z, tanh, split to bf16 hi/lo, publish local + remote halves
        #pragma unroll
        for (int p = 0; p < 4; p++) {
            int half = p >> 1, t8 = p & 1;
            float s0 = zv[p].x + acc[t8*4 + half*2 + 0];
            float s1 = zv[p].y + acc[t8*4 + half*2 + 1];
            float y0 = ftanh(s0), y1 = ftanh(s1);
            __nv_bfloat16 h0 = __float2bfloat16(y0), h1 = __float2bfloat16(y1);
            __nv_bfloat16 l0 = __float2bfloat16(y0 - __bfloat162float(h0));
            __nv_bfloat16 l1 = __float2bfloat16(y1 - __bfloat162float(h1));
            uint32_t hp = ((uint32_t)__bfloat16_as_ushort(h1) << 16) | __bfloat16_as_ushort(h0);
            uint32_t lp = ((uint32_t)__bfloat16_as_ushort(l1) << 16) | __bfloat16_as_ushort(l0);
            uint32_t la = hn + hOffPair[p];
            sts_u32(la, hp);
            sts_u32(la + 8192, lp);
            st_cluster_u32(mapa_u32(la, peer), hp);
            st_cluster_u32(mapa_u32(la + 8192, peer), lp);
            if (A.outHi) {
                size_t gi = ((size_t)t*BATCH + batch0 + mIdx[p])*HID + kgIdx[p];
                *(uint32_t*)&A.outHi[gi] = hp;
                *(uint32_t*)&A.outLo[gi] = lp;
            }
            if (A.hFinal && t == T_STEPS - 1) {
                size_t fi = (size_t)(batch0 + mIdx[p])*HID + kgIdx[p];
                A.hFinal[fi]     = y0;
                A.hFinal[fi + 1] = y1;
            }
        }
        // arrivals certify my reads of hb (WAR-safe) + order my DSMEM stores (release)
        mbar_arrive_remote_addr(rBar);
        mbar_arrive_local(barAddr);
        mbar_wait_cluster(barAddr, (uint32_t)(t & 1));
    }
    cluster_sync_();
}

// -------------------- split converters --------------------
__global__ void wsplit(const float* __restrict__ W, __nv_bfloat16* __restrict__ hi,
                       __nv_bfloat16* __restrict__ lo, int Nw, int Kw, int Kp)
{
    int i = blockIdx.x*blockDim.x + threadIdx.x;
    if (i >= 256*Kp) return;
    int r = i / Kp, c = i - r*Kp;
    float v = (r < Nw && c < Kw) ? W[r*Kw + c] : 0.f;
    __nv_bfloat16 h = __float2bfloat16(v);
    hi[i] = h;
    lo[i] = __float2bfloat16(v - __bfloat162float(h));
}

__global__ void xsplit(const float* __restrict__ src, __nv_bfloat16* __restrict__ hi,
                       __nv_bfloat16* __restrict__ lo)
{
    const size_t total = (size_t)MROWS*KP_IN;
    for (size_t i = (size_t)blockIdx.x*blockDim.x + threadIdx.x; i < total;
         i += (size_t)gridDim.x*blockDim.x) {
        size_t r = i / KP_IN;
        int c = (int)(i - r*KP_IN);
        float v = (c < IN_DIM) ? src[r*IN_DIM + c] : 0.f;
        __nv_bfloat16 h = __float2bfloat16(v);
        hi[i] = h;
        lo[i] = __float2bfloat16(v - __bfloat162float(h));
    }
}

__global__ void decsplit(const float* __restrict__ X, const float* __restrict__ Y,
                         __nv_bfloat16* __restrict__ hi, __nv_bfloat16* __restrict__ lo)
{
    const size_t total = (size_t)MROWS*KP_IN;
    for (size_t i = (size_t)blockIdx.x*blockDim.x + threadIdx.x; i < total;
         i += (size_t)gridDim.x*blockDim.x) {
        size_t r = i / KP_IN;
        int c = (int)(i - r*KP_IN);
        float v = 0.f;
        if (c < IN_DIM)
            v = (r < BATCH) ? X[((size_t)1023*BATCH + r)*IN_DIM + c]
                            : Y[(r - BATCH)*IN_DIM + c];
        __nv_bfloat16 h = __float2bfloat16(v);
        hi[i] = h;
        lo[i] = __float2bfloat16(v - __bfloat162float(h));
    }
}

// -------------------- log_softmax in place --------------------
__global__ void __launch_bounds__(256) logsoftmax_kernel(float* __restrict__ out, int rows) {
    int row = blockIdx.x*8 + (threadIdx.x >> 5);
    int lane = threadIdx.x & 31;
    if (row >= rows) return;
    float* p = out + (size_t)row*OUT_DIM;
    float v[5];
    float mx = -1e30f;
    #pragma unroll
    for (int i = 0; i < 5; i++) {
        int idx = lane + i*32;
        v[i] = (idx < OUT_DIM) ? p[idx] : -1e30f;
        mx = fmaxf(mx, v[i]);
    }
    #pragma unroll
    for (int o = 16; o > 0; o >>= 1)
        mx = fmaxf(mx, __shfl_xor_sync(0xffffffffu, mx, o));
    float s = 0.f;
    #pragma unroll
    for (int i = 0; i < 5; i++) {
        int idx = lane + i*32;
        if (idx < OUT_DIM) s += expf(v[i] - mx);
    }
    #pragma unroll
    for (int o = 16; o > 0; o >>= 1)
        s += __shfl_xor_sync(0xffffffffu, s, o);
    float lse = mx + logf(s);
    #pragma unroll
    for (int i = 0; i < 5; i++) {
        int idx = lane + i*32;
        if (idx < OUT_DIM) p[idx] = v[i] - lse;
    }
}

// -------------------- driver --------------------
extern "C" void kernel_launch(void* const* d_in, const int* in_sizes, int n_in,
                              void* d_out, int out_size) {
    const float* X     = (const float*)d_in[0];
    const float* Y     = (const float*)d_in[1];
    const float* eWih0 = (const float*)d_in[2];
    const float* eWhh0 = (const float*)d_in[3];
    const float* ebih0 = (const float*)d_in[4];
    const float* ebhh0 = (const float*)d_in[5];
    const float* eWih1 = (const float*)d_in[6];
    const float* eWhh1 = (const float*)d_in[7];
    const float* ebih1 = (const float*)d_in[8];
    const float* ebhh1 = (const float*)d_in[9];
    const float* dWih0 = (const float*)d_in[10];
    const float* dWhh0 = (const float*)d_in[11];
    const float* dbih0 = (const float*)d_in[12];
    const float* dbhh0 = (const float*)d_in[13];
    const float* dWih1 = (const float*)d_in[14];
    const float* dWhh1 = (const float*)d_in[15];
    const float* dbih1 = (const float*)d_in[16];
    const float* dbhh1 = (const float*)d_in[17];
    const float* lin_W = (const float*)d_in[18];
    const float* lin_b = (const float*)d_in[19];
    float* out = (float*)d_out;

    float *Zenc, *Zdec, *hn0, *hn1;
    __nv_bfloat16 *Hhi, *Hlo, *Xhi, *Xlo, *Dhi, *Dlo, *Wh, *Wl;
    cudaGetSymbolAddress((void**)&Zenc, g_Zenc);
    cudaGetSymbolAddress((void**)&Zdec, g_Zdec);
    cudaGetSymbolAddress((void**)&Hhi,  g_Hhi);
    cudaGetSymbolAddress((void**)&Hlo,  g_Hlo);
    cudaGetSymbolAddress((void**)&Xhi,  g_Xhi);
    cudaGetSymbolAddress((void**)&Xlo,  g_Xlo);
    cudaGetSymbolAddress((void**)&Dhi,  g_Dhi);
    cudaGetSymbolAddress((void**)&Dlo,  g_Dlo);
    cudaGetSymbolAddress((void**)&Wh,   g_Wh);
    cudaGetSymbolAddress((void**)&Wl,   g_Wl);
    cudaGetSymbolAddress((void**)&hn0,  g_hn0);
    cudaGetSymbolAddress((void**)&hn1,  g_hn1);

    cudaFuncSetAttribute((const void*)recur_mma,
                         cudaFuncAttributeMaxDynamicSharedMemorySize, R_SMEM_TOTAL);
    cudaFuncSetAttribute((const void*)gemm_mma,
                         cudaFuncAttributeMaxDynamicSharedMemorySize, GM_SMEM);

    const int WSTRIDE = 256*256;
    const dim3 gG(MROWS/128, 2);

    wsplit<<<(256*KP_IN+255)/256, 256>>>(eWih0, Wh+0*WSTRIDE, Wl+0*WSTRIDE, HID, IN_DIM, KP_IN);
    wsplit<<<(256*KP_IN+255)/256, 256>>>(dWih0, Wh+1*WSTRIDE, Wl+1*WSTRIDE, HID, IN_DIM, KP_IN);
    wsplit<<<(256*256+255)/256, 256>>>(eWih1, Wh+2*WSTRIDE, Wl+2*WSTRIDE, HID, HID, 256);
    wsplit<<<(256*256+255)/256, 256>>>(dWih1, Wh+3*WSTRIDE, Wl+3*WSTRIDE, HID, HID, 256);
    wsplit<<<(256*256+255)/256, 256>>>(lin_W, Wh+4*WSTRIDE, Wl+4*WSTRIDE, OUT_DIM, HID, 256);
    xsplit<<<4096, 256>>>(X, Xhi, Xlo);
    decsplit<<<4096, 256>>>(X, Y, Dhi, Dlo);

    // Z_enc0 / Z_dec0
    gemm_mma<<<gG, 256, GM_SMEM>>>(Xhi, Xlo, Wh+0*WSTRIDE, Wl+0*WSTRIDE,
                                   ebih0, ebhh0, Zenc, 256, KP_IN);
    gemm_mma<<<gG, 256, GM_SMEM>>>(Dhi, Dlo, Wh+1*WSTRIDE, Wl+1*WSTRIDE,
                                   dbih0, dbhh0, Zdec, 256, KP_IN);
    // encoder layer0 recurrence -> H (split), hn0
    {
        RArgs a; a.Z = Zenc; a.outHi = Hhi; a.outLo = Hlo; a.W = eWhh0; a.hInit = nullptr; a.hFinal = hn0;
        recur_mma<<<32, 256, R_SMEM_TOTAL>>>(a, a, 16);
    }
    // Z_enc1
    gemm_mma<<<gG, 256, GM_SMEM>>>(Hhi, Hlo, Wh+2*WSTRIDE, Wl+2*WSTRIDE,
                                   ebih1, ebhh1, Zenc, 256, 256);
    // encoder layer1 (-> hn1) and decoder layer0 (-> H, from hn0) concurrently
    {
        RArgs a0; a0.Z = Zenc; a0.outHi = nullptr; a0.outLo = nullptr; a0.W = eWhh1; a0.hInit = nullptr; a0.hFinal = hn1;
        RArgs a1; a1.Z = Zdec; a1.outHi = Hhi;     a1.outLo = Hlo;     a1.W = dWhh0; a1.hInit = hn0;     a1.hFinal = nullptr;
        recur_mma<<<64, 256, R_SMEM_TOTAL>>>(a0, a1, 16);
    }
    // Z_dec1
    gemm_mma<<<gG, 256, GM_SMEM>>>(Hhi, Hlo, Wh+3*WSTRIDE, Wl+3*WSTRIDE,
                                   dbih1, dbhh1, Zdec, 256, 256);
    // decoder layer1 recurrence -> H
    {
        RArgs a; a.Z = Zdec; a.outHi = Hhi; a.outLo = Hlo; a.W = dWhh1; a.hInit = hn1; a.hFinal = nullptr;
        recur_mma<<<32, 256, R_SMEM_TOTAL>>>(a, a, 16);
    }
    // logits + log_softmax
    gemm_mma<<<gG, 256, GM_SMEM>>>(Hhi, Hlo, Wh+4*WSTRIDE, Wl+4*WSTRIDE,
                                   lin_b, nullptr, out, OUT_DIM, 256);
    logsoftmax_kernel<<<(MROWS + 7)/8, 256>>>(out, MROWS);
}

// round 11
// speedup vs baseline: 1.1384x; 1.1362x over previous
#include <cuda_runtime.h>
#include <cuda_bf16.h>
#include <cstdint>
#include <cstddef>

#define SEQ 1024
#define BATCH 256
#define IN_DIM 131
#define HID 256
#define OUT_DIM 131
#define T_STEPS 1023
#define MROWS (T_STEPS*BATCH)   // 261888 = 128 * 2046
#define KP_IN 192               // padded K for IN_DIM=131 GEMMs

// -------------------- scratch: ONE union buffer (time-multiplexed) --------------------
// ZBYTES = MROWS*HID*4. Layout: [Zenc | Zdec | region3]
// region3 timeline: (Xhi,Xlo) -> (Dhi,Dlo) -> (Hhi,Hlo)   (each consumer runs before rewrite)
#define ZBYTES ((size_t)MROWS*HID*4)          // 268,173,312
__device__ char  g_buf[3*ZBYTES];
__device__ __nv_bfloat16 g_Wh[5*256*256];
__device__ __nv_bfloat16 g_Wl[5*256*256];
__device__ float g_hn0[BATCH*HID];
__device__ float g_hn1[BATCH*HID];

// -------------------- common helpers --------------------
__device__ __forceinline__ uint32_t smem_u32(const void* p) {
    return (uint32_t)__cvta_generic_to_shared(p);
}
__device__ __forceinline__ uint32_t my_ctarank() {
    uint32_t r; asm("mov.u32 %0, %%cluster_ctarank;" : "=r"(r)); return r;
}
__device__ __forceinline__ void cluster_sync_() {
    asm volatile("barrier.cluster.arrive.aligned;\n\t"
                 "barrier.cluster.wait.aligned;" ::: "memory");
}
__device__ __forceinline__ uint32_t mapa_u32(uint32_t laddr, uint32_t peer) {
    uint32_t raddr;
    asm volatile("mapa.shared::cluster.u32 %0, %1, %2;" : "=r"(raddr) : "r"(laddr), "r"(peer));
    return raddr;
}
__device__ __forceinline__ void st_cluster_f32(uint32_t raddr, float v) {
    asm volatile("st.shared::cluster.f32 [%0], %1;" :: "r"(raddr), "f"(v) : "memory");
}
__device__ __forceinline__ void mbar_init(uint32_t addr, uint32_t count) {
    asm volatile("mbarrier.init.shared.b64 [%0], %1;" :: "r"(addr), "r"(count) : "memory");
}
__device__ __forceinline__ void mbar_arrive_remote_addr(uint32_t raddr) {
    asm volatile("mbarrier.arrive.release.cluster.shared::cluster.b64 _, [%0];"
                 :: "r"(raddr) : "memory");
}
__device__ __forceinline__ void mbar_wait_cluster(uint32_t addr, uint32_t parity) {
    asm volatile(
        "{\n\t.reg .pred P;\n\t"
        "WAIT_%=:\n\t"
        "mbarrier.try_wait.parity.acquire.cluster.shared::cta.b64 P, [%0], %1, 0x989680;\n\t"
        "@P bra.uni DONE_%=;\n\t"
        "bra.uni WAIT_%=;\n\t"
        "DONE_%=:\n\t}" :: "r"(addr), "r"(parity) : "memory");
}
__device__ __forceinline__ float ftanh(float x) {
    float xc = fminf(fmaxf(x, -15.f), 15.f);
    float e = __expf(2.f*xc);
    return __fdividef(e - 1.f, e + 1.f);
}

// -------------------- mma.sync / ldmatrix primitives (compute_103-legal) --------------------
__device__ __forceinline__ uint32_t swz128(uint32_t off) {
    return off ^ ((off >> 3) & 0x70);
}
__device__ __forceinline__ void ldm4(uint32_t* r, uint32_t addr) {
    asm volatile("ldmatrix.sync.aligned.m8n8.x4.shared.b16 {%0,%1,%2,%3}, [%4];"
        : "=r"(r[0]), "=r"(r[1]), "=r"(r[2]), "=r"(r[3]) : "r"(addr));
}
__device__ __forceinline__ void mma16816(float* d, const uint32_t* a, uint32_t b0, uint32_t b1) {
    asm volatile("mma.sync.aligned.m16n8k16.row.col.f32.bf16.bf16.f32 "
        "{%0,%1,%2,%3}, {%4,%5,%6,%7}, {%8,%9}, {%0,%1,%2,%3};"
        : "+f"(d[0]), "+f"(d[1]), "+f"(d[2]), "+f"(d[3])
        : "r"(a[0]), "r"(a[1]), "r"(a[2]), "r"(a[3]), "r"(b0), "r"(b1));
}

// -------------------- tensor GEMM: C = [Ahi|Alo|Ahi] @ [Bhi|Bhi|Blo]^T + bias --------------------
#define GM_SMEM (2*16384*2)     // 65536: [buf][A 16KB | B 16KB]

__global__ void __launch_bounds__(256,1)
gemm_mma(const __nv_bfloat16* __restrict__ Ahi, const __nv_bfloat16* __restrict__ Alo,
         const __nv_bfloat16* __restrict__ Bhi, const __nv_bfloat16* __restrict__ Blo,
         const float* __restrict__ b1, const float* __restrict__ b2,
         float* __restrict__ C, int Nout, int Kp)
{
    extern __shared__ char smem[];
    const uint32_t sb = smem_u32(smem);
    const int tid = threadIdx.x;
    const int lane = tid & 31, warp = tid >> 5;
    const int wm = warp & 3, wn = warp >> 2;
    const int m0 = blockIdx.x * 128;
    const int n0 = blockIdx.y * 128;

    const int kchunks = Kp >> 6;
    const int nch = 3 * kchunks;

    int lrow[4], lcol[4];
    #pragma unroll
    for (int i = 0; i < 4; i++) {
        int lin = tid + i*256;
        lrow[i] = lin >> 3;
        lcol[i] = (lin & 7) * 16;
    }

    const int aidx = lane & 7;
    uint32_t aoff[2];
    #pragma unroll
    for (int mi = 0; mi < 2; mi++) {
        int r = wm*32 + mi*16 + aidx + ((lane >> 3) & 1)*8;
        aoff[mi] = (uint32_t)(r*128 + ((lane >> 4) & 1)*16);
    }
    uint32_t boff[4];
    #pragma unroll
    for (int j = 0; j < 4; j++) {
        int r = wn*64 + j*16 + aidx + ((lane >> 4) & 1)*8;
        boff[j] = (uint32_t)(r*128 + ((lane >> 3) & 1)*16);
    }

    float acc[2][8][4];
    #pragma unroll
    for (int mi = 0; mi < 2; mi++)
        #pragma unroll
        for (int ni = 0; ni < 8; ni++)
            #pragma unroll
            for (int q = 0; q < 4; q++) acc[mi][ni][q] = 0.f;

    uint4 ra[4], rb[4];
    auto srcA = [&](int c) -> const __nv_bfloat16* {
        int pass = c / kchunks; return (pass == 1) ? Alo : Ahi;
    };
    auto srcB = [&](int c) -> const __nv_bfloat16* {
        int pass = c / kchunks; return (pass == 2) ? Blo : Bhi;
    };
    auto kcOf = [&](int c) -> int { int pass = c / kchunks; return c - pass*kchunks; };

    {
        const __nv_bfloat16* Ap = srcA(0);
        const __nv_bfloat16* Bp = srcB(0);
        #pragma unroll
        for (int i = 0; i < 4; i++) {
            ra[i] = *(const uint4*)((const char*)Ap + ((size_t)(m0 + lrow[i])*Kp)*2 + lcol[i]);
            rb[i] = *(const uint4*)((const char*)Bp + ((size_t)(n0 + lrow[i])*Kp)*2 + lcol[i]);
        }
        #pragma unroll
        for (int i = 0; i < 4; i++) {
            *(uint4*)(smem + swz128((uint32_t)(lrow[i]*128 + lcol[i]))) = ra[i];
            *(uint4*)(smem + 16384 + swz128((uint32_t)(lrow[i]*128 + lcol[i]))) = rb[i];
        }
    }
    __syncthreads();

    for (int c = 0; c < nch; ++c) {
        const int buf = c & 1;
        const uint32_t aB = sb + buf*32768;
        const uint32_t bB = sb + buf*32768 + 16384;

        if (c + 1 < nch) {
            const __nv_bfloat16* Ap = srcA(c+1);
            const __nv_bfloat16* Bp = srcB(c+1);
            const int kc = kcOf(c+1);
            #pragma unroll
            for (int i = 0; i < 4; i++) {
                ra[i] = *(const uint4*)((const char*)Ap + ((size_t)(m0 + lrow[i])*Kp)*2 + kc*128 + lcol[i]);
                rb[i] = *(const uint4*)((const char*)Bp + ((size_t)(n0 + lrow[i])*Kp)*2 + kc*128 + lcol[i]);
            }
        }

        #pragma unroll
        for (int ks = 0; ks < 4; ks++) {
            uint32_t afr[2][4];
            #pragma unroll
            for (int mi = 0; mi < 2; mi++)
                ldm4(afr[mi], aB + swz128(aoff[mi] + ks*32));
            #pragma unroll
            for (int j = 0; j < 4; j++) {
                uint32_t bfr[4];
                ldm4(bfr, bB + swz128(boff[j] + ks*32));
                #pragma unroll
                for (int mi = 0; mi < 2; mi++) {
                    mma16816(acc[mi][2*j],   afr[mi], bfr[0], bfr[1]);
                    mma16816(acc[mi][2*j+1], afr[mi], bfr[2], bfr[3]);
                }
            }
        }

        if (c + 1 < nch) {
            char* ag = smem + (buf ^ 1)*32768;
            char* bg = smem + (buf ^ 1)*32768 + 16384;
            #pragma unroll
            for (int i = 0; i < 4; i++) {
                *(uint4*)(ag + swz128((uint32_t)(lrow[i]*128 + lcol[i]))) = ra[i];
                *(uint4*)(bg + swz128((uint32_t)(lrow[i]*128 + lcol[i]))) = rb[i];
            }
        }
        __syncthreads();
    }

    const int er = lane >> 2, ec = (lane & 3) * 2;
    #pragma unroll
    for (int mi = 0; mi < 2; mi++) {
        #pragma unroll
        for (int ni = 0; ni < 8; ni++) {
            const int nbase = n0 + wn*64 + ni*8 + ec;
            const int mbase = m0 + wm*32 + mi*16 + er;
            #pragma unroll
            for (int half = 0; half < 2; half++) {
                int m = mbase + half*8;
                #pragma unroll
                for (int q = 0; q < 2; q++) {
                    int n = nbase + q;
                    if (n < Nout) {
                        float bias = __ldg(&b1[n]) + (b2 ? __ldg(&b2[n]) : 0.f);
                        C[(size_t)m*Nout + n] = acc[mi][ni][half*2 + q] + bias;
                    }
                }
            }
        }
    }
}

// -------------------- recurrence: h_t = tanh(Z_t + h_{t-1} @ Whh^T) --------------------
// 2-CTA cluster; each CTA holds 128 j-rows of Whh transposed in SMEM (proven R5 layout).
// Sync: ONE remote mbarrier arrive per warp (after __syncwarp; release cumulativity
// covers all lanes' DSMEM stores); local ordering via __syncthreads. Barrier counts
// only the peer's 8 warp-arrivals.
struct RArgs {
    const float*   Z;       // [T, BATCH, HID] pre-projected input (incl. both biases)
    __nv_bfloat16* outHi;   // nullable: split-bf16 sequence output
    __nv_bfloat16* outLo;
    const float*   W;       // Whh [HID, HID]
    const float*   hInit;   // nullable -> zeros
    float*         hFinal;  // nullable
};

#define RECUR_SMEM(RBB) ((4 + 128*HID + 2*(RBB)*HID + 4*(RBB)*128)*4)

template<int RBB>
__global__ void __launch_bounds__(256,1) __cluster_dims__(2,1,1)
recur_kernel(RArgs a0, RArgs a1, int nClustA)
{
    extern __shared__ float smemf[];
    float* sW = smemf + 4;                 // [k][j] transposed, 128*256
    float* sH = sW + 128*HID;              // 2 * RBB * 256 (double buffer)
    float* sP = sH + 2*RBB*HID;            // [4][RBB][128] partials

    const int tid = threadIdx.x;
    const uint32_t rank = my_ctarank();
    const uint32_t peer = rank ^ 1u;
    const int cid = (int)(blockIdx.x >> 1);
    const bool isA = (cid < nClustA);
    RArgs A = isA ? a0 : a1;
    const int batch0 = (isA ? cid : (cid - nClustA)) * RBB;
    const uint32_t barAddr = smem_u32(smemf);

    if (tid == 0) mbar_init(barAddr, 8);   // 8 PEER warp-arrivals per step

    // Load weight slice transposed: sW[k*128 + j] = W[(rank*128+j)*HID + k]
    for (int idx = tid; idx < 128*HID; idx += 256) {
        int j = idx >> 8;
        int k = idx & 255;
        sW[k*128 + j] = A.W[((size_t)(rank*128 + j))*HID + k];
    }
    for (int idx = tid; idx < RBB*HID; idx += 256)
        sH[idx] = A.hInit ? A.hInit[(size_t)batch0*HID + idx] : 0.f;

    // loop-invariant remote addresses
    const uint32_t rBar = mapa_u32(barAddr, peer);
    uint32_t rHn[2][RBB/2];
    float*   lHn[2][RBB/2];
    int      bOf[RBB/2], jOf[RBB/2];
    #pragma unroll
    for (int i = 0; i < RBB/2; i++) {
        int o = tid + i*256;
        int b = o >> 7, jj = o & 127;
        bOf[i] = b; jOf[i] = jj;
        #pragma unroll
        for (int buf = 0; buf < 2; buf++) {
            float* dst = sH + buf*RBB*HID + b*HID + (int)rank*128 + jj;
            lHn[buf][i] = dst;
            rHn[buf][i] = mapa_u32(smem_u32(dst), peer);
        }
    }

    __syncthreads();
    cluster_sync_();   // barrier init + W/h visible cluster-wide

    const int jp = tid & 63;
    const int ks = tid >> 6;
    const int kbase = ks*64;

    for (int t = 0; t < T_STEPS; ++t) {
        const float* hc = sH + (t & 1)*RBB*HID;
        const int nbuf = (t + 1) & 1;

        // epilogue Z prefetch (issued before compute; latency hidden)
        float zreg[RBB/2];
        const float* Zt = A.Z + ((size_t)t*BATCH + batch0)*HID;
        #pragma unroll
        for (int i = 0; i < RBB/2; i++)
            zreg[i] = Zt[bOf[i]*HID + (int)rank*128 + jOf[i]];

        float2 acc[RBB];
        #pragma unroll
        for (int b = 0; b < RBB; b++) { acc[b].x = 0.f; acc[b].y = 0.f; }

        #pragma unroll 1
        for (int k4 = kbase; k4 < kbase + 64; k4 += 4) {
            float4 hv[RBB];
            #pragma unroll
            for (int b = 0; b < RBB; b++)
                hv[b] = *(const float4*)&hc[b*HID + k4];     // warp-uniform broadcast
            #pragma unroll
            for (int u = 0; u < 4; u++) {
                float2 w = *(const float2*)&sW[(k4+u)*128 + 2*jp];
                #pragma unroll
                for (int b = 0; b < RBB; b++) {
                    float hvu = (u==0)?hv[b].x:(u==1)?hv[b].y:(u==2)?hv[b].z:hv[b].w;
                    acc[b].x = fmaf(w.x, hvu, acc[b].x);
                    acc[b].y = fmaf(w.y, hvu, acc[b].y);
                }
            }
        }
        #pragma unroll
        for (int b = 0; b < RBB; b++)
            ((float2*)sP)[(ks*RBB + b)*64 + jp] = acc[b];
        __syncthreads();

        // epilogue: reduce 4 slice-partials, add Z, tanh, publish local+remote
        #pragma unroll
        for (int i = 0; i < RBB/2; i++) {
            float s = zreg[i];
            #pragma unroll
            for (int p = 0; p < 4; p++)
                s += sP[(p*RBB + bOf[i])*128 + jOf[i]];
            float y = ftanh(s);
            *lHn[nbuf][i] = y;
            st_cluster_f32(rHn[nbuf][i], y);
            if (A.outHi) {
                size_t gi = ((size_t)t*BATCH + batch0 + bOf[i])*HID + (int)rank*128 + jOf[i];
                __nv_bfloat16 h = __float2bfloat16(y);
                A.outHi[gi] = h;
                A.outLo[gi] = __float2bfloat16(y - __bfloat162float(h));
            }
            if (A.hFinal && t == T_STEPS-1)
                A.hFinal[(size_t)(batch0 + bOf[i])*HID + (int)rank*128 + jOf[i]] = y;
        }
        // one release-arrive per warp: __syncwarp orders all lanes' DSMEM stores
        // before lane 0's cumulative release arrive on the peer's barrier.
        __syncwarp();
        if ((tid & 31) == 0) mbar_arrive_remote_addr(rBar);
        __syncthreads();                           // local hn visibility + step barrier
        mbar_wait_cluster(barAddr, (uint32_t)(t & 1));   // peer's 8 warp-arrivals
    }
    cluster_sync_();   // keep SMEM alive for peer's in-flight DSMEM writes
}

// -------------------- split converters --------------------
__global__ void wsplit(const float* __restrict__ W, __nv_bfloat16* __restrict__ hi,
                       __nv_bfloat16* __restrict__ lo, int Nw, int Kw, int Kp)
{
    int i = blockIdx.x*blockDim.x + threadIdx.x;
    if (i >= 256*Kp) return;
    int r = i / Kp, c = i - r*Kp;
    float v = (r < Nw && c < Kw) ? W[r*Kw + c] : 0.f;
    __nv_bfloat16 h = __float2bfloat16(v);
    hi[i] = h;
    lo[i] = __float2bfloat16(v - __bfloat162float(h));
}

__global__ void xsplit(const float* __restrict__ src, __nv_bfloat16* __restrict__ hi,
                       __nv_bfloat16* __restrict__ lo)
{
    const size_t total = (size_t)MROWS*KP_IN;
    for (size_t i = (size_t)blockIdx.x*blockDim.x + threadIdx.x; i < total;
         i += (size_t)gridDim.x*blockDim.x) {
        size_t r = i / KP_IN;
        int c = (int)(i - r*KP_IN);
        float v = (c < IN_DIM) ? src[r*IN_DIM + c] : 0.f;
        __nv_bfloat16 h = __float2bfloat16(v);
        hi[i] = h;
        lo[i] = __float2bfloat16(v - __bfloat162float(h));
    }
}

__global__ void decsplit(const float* __restrict__ X, const float* __restrict__ Y,
                         __nv_bfloat16* __restrict__ hi, __nv_bfloat16* __restrict__ lo)
{
    const size_t total = (size_t)MROWS*KP_IN;
    for (size_t i = (size_t)blockIdx.x*blockDim.x + threadIdx.x; i < total;
         i += (size_t)gridDim.x*blockDim.x) {
        size_t r = i / KP_IN;
        int c = (int)(i - r*KP_IN);
        float v = 0.f;
        if (c < IN_DIM)
            v = (r < BATCH) ? X[((size_t)1023*BATCH + r)*IN_DIM + c]
                            : Y[(r - BATCH)*IN_DIM + c];
        __nv_bfloat16 h = __float2bfloat16(v);
        hi[i] = h;
        lo[i] = __float2bfloat16(v - __bfloat162float(h));
    }
}

// -------------------- log_softmax in place --------------------
__global__ void __launch_bounds__(256) logsoftmax_kernel(float* __restrict__ out, int rows) {
    int row = blockIdx.x*8 + (threadIdx.x >> 5);
    int lane = threadIdx.x & 31;
    if (row >= rows) return;
    float* p = out + (size_t)row*OUT_DIM;
    float v[5];
    float mx = -1e30f;
    #pragma unroll
    for (int i = 0; i < 5; i++) {
        int idx = lane + i*32;
        v[i] = (idx < OUT_DIM) ? p[idx] : -1e30f;
        mx = fmaxf(mx, v[i]);
    }
    #pragma unroll
    for (int o = 16; o > 0; o >>= 1)
        mx = fmaxf(mx, __shfl_xor_sync(0xffffffffu, mx, o));
    float s = 0.f;
    #pragma unroll
    for (int i = 0; i < 5; i++) {
        int idx = lane + i*32;
        if (idx < OUT_DIM) s += expf(v[i] - mx);
    }
    #pragma unroll
    for (int o = 16; o > 0; o >>= 1)
        s += __shfl_xor_sync(0xffffffffu, s, o);
    float lse = mx + logf(s);
    #pragma unroll
    for (int i = 0; i < 5; i++) {
        int idx = lane + i*32;
        if (idx < OUT_DIM) p[idx] = v[i] - lse;
    }
}

// -------------------- driver --------------------
extern "C" void kernel_launch(void* const* d_in, const int* in_sizes, int n_in,
                              void* d_out, int out_size) {
    const float* X     = (const float*)d_in[0];
    const float* Y     = (const float*)d_in[1];
    const float* eWih0 = (const float*)d_in[2];
    const float* eWhh0 = (const float*)d_in[3];
    const float* ebih0 = (const float*)d_in[4];
    const float* ebhh0 = (const float*)d_in[5];
    const float* eWih1 = (const float*)d_in[6];
    const float* eWhh1 = (const float*)d_in[7];
    const float* ebih1 = (const float*)d_in[8];
    const float* ebhh1 = (const float*)d_in[9];
    const float* dWih0 = (const float*)d_in[10];
    const float* dWhh0 = (const float*)d_in[11];
    const float* dbih0 = (const float*)d_in[12];
    const float* dbhh0 = (const float*)d_in[13];
    const float* dWih1 = (const float*)d_in[14];
    const float* dWhh1 = (const float*)d_in[15];
    const float* dbih1 = (const float*)d_in[16];
    const float* dbhh1 = (const float*)d_in[17];
    const float* lin_W = (const float*)d_in[18];
    const float* lin_b = (const float*)d_in[19];
    float* out = (float*)d_out;

    char* buf;
    float *hn0, *hn1;
    __nv_bfloat16 *Wh, *Wl;
    cudaGetSymbolAddress((void**)&buf, g_buf);
    cudaGetSymbolAddress((void**)&Wh,  g_Wh);
    cudaGetSymbolAddress((void**)&Wl,  g_Wl);
    cudaGetSymbolAddress((void**)&hn0, g_hn0);
    cudaGetSymbolAddress((void**)&hn1, g_hn1);

    // union layout
    float* Zenc = (float*)(buf);
    float* Zdec = (float*)(buf + ZBYTES);
    char*  r3   = buf + 2*ZBYTES;                 // region 3 (time-multiplexed)
    const size_t HBYTES = (size_t)MROWS*HID*2;    // bf16 plane
    const size_t XBYTES = (size_t)MROWS*KP_IN*2;  // bf16 plane
    __nv_bfloat16* Hhi = (__nv_bfloat16*)(r3);
    __nv_bfloat16* Hlo = (__nv_bfloat16*)(r3 + HBYTES);
    __nv_bfloat16* Xhi = (__nv_bfloat16*)(r3);            // aliases Hhi (earlier lifetime)
    __nv_bfloat16* Xlo = (__nv_bfloat16*)(r3 + XBYTES);
    __nv_bfloat16* Dhi = Xhi;                             // aliases X (sequential lifetime)
    __nv_bfloat16* Dlo = Xlo;

    cudaFuncSetAttribute((const void*)recur_kernel<4>,
                         cudaFuncAttributeMaxDynamicSharedMemorySize, RECUR_SMEM(4));
    cudaFuncSetAttribute((const void*)recur_kernel<8>,
                         cudaFuncAttributeMaxDynamicSharedMemorySize, RECUR_SMEM(8));
    cudaFuncSetAttribute((const void*)gemm_mma,
                         cudaFuncAttributeMaxDynamicSharedMemorySize, GM_SMEM);

    const int WSTRIDE = 256*256;
    const dim3 gG(MROWS/128, 2);

    // weight splits (small, independent)
    wsplit<<<(256*KP_IN+255)/256, 256>>>(eWih0, Wh+0*WSTRIDE, Wl+0*WSTRIDE, HID, IN_DIM, KP_IN);
    wsplit<<<(256*KP_IN+255)/256, 256>>>(dWih0, Wh+1*WSTRIDE, Wl+1*WSTRIDE, HID, IN_DIM, KP_IN);
    wsplit<<<(256*256+255)/256, 256>>>(eWih1, Wh+2*WSTRIDE, Wl+2*WSTRIDE, HID, HID, 256);
    wsplit<<<(256*256+255)/256, 256>>>(dWih1, Wh+3*WSTRIDE, Wl+3*WSTRIDE, HID, HID, 256);
    wsplit<<<(256*256+255)/256, 256>>>(lin_W, Wh+4*WSTRIDE, Wl+4*WSTRIDE, OUT_DIM, HID, 256);

    // region3 = X split; Z_enc0 GEMM consumes it
    xsplit<<<4096, 256>>>(X, Xhi, Xlo);
    gemm_mma<<<gG, 256, GM_SMEM>>>(Xhi, Xlo, Wh+0*WSTRIDE, Wl+0*WSTRIDE,
                                   ebih0, ebhh0, Zenc, 256, KP_IN);
    // region3 = dec_in split; Z_dec0 GEMM consumes it
    decsplit<<<4096, 256>>>(X, Y, Dhi, Dlo);
    gemm_mma<<<gG, 256, GM_SMEM>>>(Dhi, Dlo, Wh+1*WSTRIDE, Wl+1*WSTRIDE,
                                   dbih0, dbhh0, Zdec, 256, KP_IN);
    // region3 = H from here on
    {
        RArgs a; a.Z = Zenc; a.outHi = Hhi; a.outLo = Hlo; a.W = eWhh0; a.hInit = nullptr; a.hFinal = hn0;
        recur_kernel<4><<<128, 256, RECUR_SMEM(4)>>>(a, a, 64);
    }
    gemm_mma<<<gG, 256, GM_SMEM>>>(Hhi, Hlo, Wh+2*WSTRIDE, Wl+2*WSTRIDE,
                                   ebih1, ebhh1, Zenc, 256, 256);
    {
        RArgs a0; a0.Z = Zenc; a0.outHi = nullptr; a0.outLo = nullptr; a0.W = eWhh1; a0.hInit = nullptr; a0.hFinal = hn1;
        RArgs a1; a1.Z = Zdec; a1.outHi = Hhi;     a1.outLo = Hlo;     a1.W = dWhh0; a1.hInit = hn0;     a1.hFinal = nullptr;
        recur_kernel<8><<<128, 256, RECUR_SMEM(8)>>>(a0, a1, 32);
    }
    gemm_mma<<<gG, 256, GM_SMEM>>>(Hhi, Hlo, Wh+3*WSTRIDE, Wl+3*WSTRIDE,
                                   dbih1, dbhh1, Zdec, 256, 256);
    {
        RArgs a; a.Z = Zdec; a.outHi = Hhi; a.outLo = Hlo; a.W = dWhh1; a.hInit = hn1; a.hFinal = nullptr;
        recur_kernel<4><<<128, 256, RECUR_SMEM(4)>>>(a, a, 64);
    }
    gemm_mma<<<gG, 256, GM_SMEM>>>(Hhi, Hlo, Wh+4*WSTRIDE, Wl+4*WSTRIDE,
                                   lin_b, nullptr, out, OUT_DIM, 256);
    logsoftmax_kernel<<<(MROWS + 7)/8, 256>>>(out, MROWS);
}

// round 12
// speedup vs baseline: 1.1653x; 1.0237x over previous
#include <cuda_runtime.h>
#include <cuda_bf16.h>
#include <cstdint>
#include <cstddef>

#define SEQ 1024
#define BATCH 256
#define IN_DIM 131
#define HID 256
#define OUT_DIM 131
#define T_STEPS 1023
#define MROWS (T_STEPS*BATCH)   // 261888 = 128 * 2046
#define KP_IN 192               // padded K for IN_DIM=131 GEMMs

// -------------------- scratch: ONE union buffer (time-multiplexed) --------------------
// ZBYTES = MROWS*HID*4. Layout: [Zenc | Zdec | region3]
// region3 timeline: (Xhi,Xlo) -> (Dhi,Dlo) -> (Hhi,Hlo)
#define ZBYTES ((size_t)MROWS*HID*4)
__device__ char  g_buf[3*ZBYTES];
__device__ __nv_bfloat16 g_Wh[5*256*256];
__device__ __nv_bfloat16 g_Wl[5*256*256];
__device__ float g_hn0[BATCH*HID];
__device__ float g_hn1[BATCH*HID];

// -------------------- common helpers --------------------
__device__ __forceinline__ uint32_t smem_u32(const void* p) {
    return (uint32_t)__cvta_generic_to_shared(p);
}
__device__ __forceinline__ uint32_t my_ctarank() {
    uint32_t r; asm("mov.u32 %0, %%cluster_ctarank;" : "=r"(r)); return r;
}
__device__ __forceinline__ void cluster_sync_() {
    asm volatile("barrier.cluster.arrive.aligned;\n\t"
                 "barrier.cluster.wait.aligned;" ::: "memory");
}
__device__ __forceinline__ uint32_t mapa_u32(uint32_t laddr, uint32_t peer) {
    uint32_t raddr;
    asm volatile("mapa.shared::cluster.u32 %0, %1, %2;" : "=r"(raddr) : "r"(laddr), "r"(peer));
    return raddr;
}
__device__ __forceinline__ void st_cluster_f32(uint32_t raddr, float v) {
    asm volatile("st.shared::cluster.f32 [%0], %1;" :: "r"(raddr), "f"(v) : "memory");
}
__device__ __forceinline__ void mbar_init(uint32_t addr, uint32_t count) {
    asm volatile("mbarrier.init.shared.b64 [%0], %1;" :: "r"(addr), "r"(count) : "memory");
}
__device__ __forceinline__ void mbar_arrive_local(uint32_t addr) {
    asm volatile("mbarrier.arrive.shared.b64 _, [%0];" :: "r"(addr) : "memory");
}
__device__ __forceinline__ void mbar_arrive_remote_addr(uint32_t raddr) {
    asm volatile("mbarrier.arrive.release.cluster.shared::cluster.b64 _, [%0];"
                 :: "r"(raddr) : "memory");
}
__device__ __forceinline__ void mbar_wait_cluster(uint32_t addr, uint32_t parity) {
    asm volatile(
        "{\n\t.reg .pred P;\n\t"
        "WAIT_%=:\n\t"
        "mbarrier.try_wait.parity.acquire.cluster.shared::cta.b64 P, [%0], %1, 0x989680;\n\t"
        "@P bra.uni DONE_%=;\n\t"
        "bra.uni WAIT_%=;\n\t"
        "DONE_%=:\n\t}" :: "r"(addr), "r"(parity) : "memory");
}
__device__ __forceinline__ float ftanh(float x) {
    float xc = fminf(fmaxf(x, -15.f), 15.f);
    float e = __expf(2.f*xc);
    return __fdividef(e - 1.f, e + 1.f);
}

// -------------------- mma.sync / ldmatrix primitives (compute_103-legal) --------------------
__device__ __forceinline__ uint32_t swz128(uint32_t off) {
    return off ^ ((off >> 3) & 0x70);
}
__device__ __forceinline__ void ldm4(uint32_t* r, uint32_t addr) {
    asm volatile("ldmatrix.sync.aligned.m8n8.x4.shared.b16 {%0,%1,%2,%3}, [%4];"
        : "=r"(r[0]), "=r"(r[1]), "=r"(r[2]), "=r"(r[3]) : "r"(addr));
}
__device__ __forceinline__ void mma16816(float* d, const uint32_t* a, uint32_t b0, uint32_t b1) {
    asm volatile("mma.sync.aligned.m16n8k16.row.col.f32.bf16.bf16.f32 "
        "{%0,%1,%2,%3}, {%4,%5,%6,%7}, {%8,%9}, {%0,%1,%2,%3};"
        : "+f"(d[0]), "+f"(d[1]), "+f"(d[2]), "+f"(d[3])
        : "r"(a[0]), "r"(a[1]), "r"(a[2]), "r"(a[3]), "r"(b0), "r"(b1));
}

// -------------------- tensor GEMM: C = [Ahi|Alo|Ahi] @ [Bhi|Bhi|Blo]^T + bias --------------------
#define GM_SMEM (2*16384*2)     // 65536: [buf][A 16KB | B 16KB]

__global__ void __launch_bounds__(256,1)
gemm_mma(const __nv_bfloat16* __restrict__ Ahi, const __nv_bfloat16* __restrict__ Alo,
         const __nv_bfloat16* __restrict__ Bhi, const __nv_bfloat16* __restrict__ Blo,
         const float* __restrict__ b1, const float* __restrict__ b2,
         float* __restrict__ C, int Nout, int Kp)
{
    extern __shared__ char smem[];
    const uint32_t sb = smem_u32(smem);
    const int tid = threadIdx.x;
    const int lane = tid & 31, warp = tid >> 5;
    const int wm = warp & 3, wn = warp >> 2;
    const int m0 = blockIdx.x * 128;
    const int n0 = blockIdx.y * 128;

    const int kchunks = Kp >> 6;
    const int nch = 3 * kchunks;

    int lrow[4], lcol[4];
    #pragma unroll
    for (int i = 0; i < 4; i++) {
        int lin = tid + i*256;
        lrow[i] = lin >> 3;
        lcol[i] = (lin & 7) * 16;
    }

    const int aidx = lane & 7;
    uint32_t aoff[2];
    #pragma unroll
    for (int mi = 0; mi < 2; mi++) {
        int r = wm*32 + mi*16 + aidx + ((lane >> 3) & 1)*8;
        aoff[mi] = (uint32_t)(r*128 + ((lane >> 4) & 1)*16);
    }
    uint32_t boff[4];
    #pragma unroll
    for (int j = 0; j < 4; j++) {
        int r = wn*64 + j*16 + aidx + ((lane >> 4) & 1)*8;
        boff[j] = (uint32_t)(r*128 + ((lane >> 3) & 1)*16);
    }

    float acc[2][8][4];
    #pragma unroll
    for (int mi = 0; mi < 2; mi++)
        #pragma unroll
        for (int ni = 0; ni < 8; ni++)
            #pragma unroll
            for (int q = 0; q < 4; q++) acc[mi][ni][q] = 0.f;

    uint4 ra[4], rb[4];
    auto srcA = [&](int c) -> const __nv_bfloat16* {
        int pass = c / kchunks; return (pass == 1) ? Alo : Ahi;
    };
    auto srcB = [&](int c) -> const __nv_bfloat16* {
        int pass = c / kchunks; return (pass == 2) ? Blo : Bhi;
    };
    auto kcOf = [&](int c) -> int { int pass = c / kchunks; return c - pass*kchunks; };

    {
        const __nv_bfloat16* Ap = srcA(0);
        const __nv_bfloat16* Bp = srcB(0);
        #pragma unroll
        for (int i = 0; i < 4; i++) {
            ra[i] = *(const uint4*)((const char*)Ap + ((size_t)(m0 + lrow[i])*Kp)*2 + lcol[i]);
            rb[i] = *(const uint4*)((const char*)Bp + ((size_t)(n0 + lrow[i])*Kp)*2 + lcol[i]);
        }
        #pragma unroll
        for (int i = 0; i < 4; i++) {
            *(uint4*)(smem + swz128((uint32_t)(lrow[i]*128 + lcol[i]))) = ra[i];
            *(uint4*)(smem + 16384 + swz128((uint32_t)(lrow[i]*128 + lcol[i]))) = rb[i];
        }
    }
    __syncthreads();

    for (int c = 0; c < nch; ++c) {
        const int buf = c & 1;
        const uint32_t aB = sb + buf*32768;
        const uint32_t bB = sb + buf*32768 + 16384;

        if (c + 1 < nch) {
            const __nv_bfloat16* Ap = srcA(c+1);
            const __nv_bfloat16* Bp = srcB(c+1);
            const int kc = kcOf(c+1);
            #pragma unroll
            for (int i = 0; i < 4; i++) {
                ra[i] = *(const uint4*)((const char*)Ap + ((size_t)(m0 + lrow[i])*Kp)*2 + kc*128 + lcol[i]);
                rb[i] = *(const uint4*)((const char*)Bp + ((size_t)(n0 + lrow[i])*Kp)*2 + kc*128 + lcol[i]);
            }
        }

        #pragma unroll
        for (int ks = 0; ks < 4; ks++) {
            uint32_t afr[2][4];
            #pragma unroll
            for (int mi = 0; mi < 2; mi++)
                ldm4(afr[mi], aB + swz128(aoff[mi] + ks*32));
            #pragma unroll
            for (int j = 0; j < 4; j++) {
                uint32_t bfr[4];
                ldm4(bfr, bB + swz128(boff[j] + ks*32));
                #pragma unroll
                for (int mi = 0; mi < 2; mi++) {
                    mma16816(acc[mi][2*j],   afr[mi], bfr[0], bfr[1]);
                    mma16816(acc[mi][2*j+1], afr[mi], bfr[2], bfr[3]);
                }
            }
        }

        if (c + 1 < nch) {
            char* ag = smem + (buf ^ 1)*32768;
            char* bg = smem + (buf ^ 1)*32768 + 16384;
            #pragma unroll
            for (int i = 0; i < 4; i++) {
                *(uint4*)(ag + swz128((uint32_t)(lrow[i]*128 + lcol[i]))) = ra[i];
                *(uint4*)(bg + swz128((uint32_t)(lrow[i]*128 + lcol[i]))) = rb[i];
            }
        }
        __syncthreads();
    }

    const int er = lane >> 2, ec = (lane & 3) * 2;
    #pragma unroll
    for (int mi = 0; mi < 2; mi++) {
        #pragma unroll
        for (int ni = 0; ni < 8; ni++) {
            const int nbase = n0 + wn*64 + ni*8 + ec;
            const int mbase = m0 + wm*32 + mi*16 + er;
            #pragma unroll
            for (int half = 0; half < 2; half++) {
                int m = mbase + half*8;
                #pragma unroll
                for (int q = 0; q < 2; q++) {
                    int n = nbase + q;
                    if (n < Nout) {
                        float bias = __ldg(&b1[n]) + (b2 ? __ldg(&b2[n]) : 0.f);
                        C[(size_t)m*Nout + n] = acc[mi][ni][half*2 + q] + bias;
                    }
                }
            }
        }
    }
}

// -------------------- recurrence: h_t = tanh(Z_t + h_{t-1} @ Whh^T) --------------------
// EXACT R5 sync protocol (512-count mbarrier, per-thread remote+local arrives).
// NEW: matvec k-loop unrolled (4 for RBB=4, 2 for RBB=8) to batch LDS and fill
// issue bubbles (measured issue=43% with unroll 1).
struct RArgs {
    const float*   Z;
    __nv_bfloat16* outHi;
    __nv_bfloat16* outLo;
    const float*   W;
    const float*   hInit;
    float*         hFinal;
};

#define RECUR_SMEM(RBB) ((4 + 128*HID + 2*(RBB)*HID + 4*(RBB)*128)*4)

#define MATVEC_STEP(K4) do {                                              \
    float4 hv[RBB];                                                       \
    _Pragma("unroll")                                                     \
    for (int b = 0; b < RBB; b++)                                         \
        hv[b] = *(const float4*)&hc[b*HID + (K4)];                        \
    _Pragma("unroll")                                                     \
    for (int u = 0; u < 4; u++) {                                         \
        float2 w = *(const float2*)&sW[((K4)+u)*128 + 2*jp];              \
        _Pragma("unroll")                                                 \
        for (int b = 0; b < RBB; b++) {                                   \
            float hvu = (u==0)?hv[b].x:(u==1)?hv[b].y:(u==2)?hv[b].z:hv[b].w; \
            acc[b].x = fmaf(w.x, hvu, acc[b].x);                          \
            acc[b].y = fmaf(w.y, hvu, acc[b].y);                          \
        }                                                                 \
    }                                                                     \
} while (0)

template<int RBB>
__global__ void __launch_bounds__(256,1) __cluster_dims__(2,1,1)
recur_kernel(RArgs a0, RArgs a1, int nClustA)
{
    extern __shared__ float smemf[];
    float* sW = smemf + 4;                 // [k][j] transposed, 128*256
    float* sH = sW + 128*HID;              // 2 * RBB * 256 (double buffer)
    float* sP = sH + 2*RBB*HID;            // [4][RBB][128] partials

    const int tid = threadIdx.x;
    const uint32_t rank = my_ctarank();
    const uint32_t peer = rank ^ 1u;
    const int cid = (int)(blockIdx.x >> 1);
    const bool isA = (cid < nClustA);
    RArgs A = isA ? a0 : a1;
    const int batch0 = (isA ? cid : (cid - nClustA)) * RBB;
    const uint32_t barAddr = smem_u32(smemf);

    if (tid == 0) mbar_init(barAddr, 512);

    for (int idx = tid; idx < 128*HID; idx += 256) {
        int j = idx >> 8;
        int k = idx & 255;
        sW[k*128 + j] = A.W[((size_t)(rank*128 + j))*HID + k];
    }
    for (int idx = tid; idx < RBB*HID; idx += 256)
        sH[idx] = A.hInit ? A.hInit[(size_t)batch0*HID + idx] : 0.f;

    const uint32_t rBar = mapa_u32(barAddr, peer);
    uint32_t rHn[2][RBB/2];
    float*   lHn[2][RBB/2];
    int      bOf[RBB/2], jOf[RBB/2];
    #pragma unroll
    for (int i = 0; i < RBB/2; i++) {
        int o = tid + i*256;
        int b = o >> 7, jj = o & 127;
        bOf[i] = b; jOf[i] = jj;
        #pragma unroll
        for (int buf = 0; buf < 2; buf++) {
            float* dst = sH + buf*RBB*HID + b*HID + (int)rank*128 + jj;
            lHn[buf][i] = dst;
            rHn[buf][i] = mapa_u32(smem_u32(dst), peer);
        }
    }

    __syncthreads();
    cluster_sync_();

    const int jp = tid & 63;
    const int ks = tid >> 6;
    const int kbase = ks*64;

    for (int t = 0; t < T_STEPS; ++t) {
        const float* hc = sH + (t & 1)*RBB*HID;
        const int nbuf = (t + 1) & 1;

        float zreg[RBB/2];
        const float* Zt = A.Z + ((size_t)t*BATCH + batch0)*HID;
        #pragma unroll
        for (int i = 0; i < RBB/2; i++)
            zreg[i] = Zt[bOf[i]*HID + (int)rank*128 + jOf[i]];

        float2 acc[RBB];
        #pragma unroll
        for (int b = 0; b < RBB; b++) { acc[b].x = 0.f; acc[b].y = 0.f; }

        if constexpr (RBB <= 4) {
            #pragma unroll 4
            for (int k4 = kbase; k4 < kbase + 64; k4 += 4)
                MATVEC_STEP(k4);
        } else {
            #pragma unroll 2
            for (int k4 = kbase; k4 < kbase + 64; k4 += 4)
                MATVEC_STEP(k4);
        }
        #pragma unroll
        for (int b = 0; b < RBB; b++)
            ((float2*)sP)[(ks*RBB + b)*64 + jp] = acc[b];
        __syncthreads();

        #pragma unroll
        for (int i = 0; i < RBB/2; i++) {
            float s = zreg[i];
            #pragma unroll
            for (int p = 0; p < 4; p++)
                s += sP[(p*RBB + bOf[i])*128 + jOf[i]];
            float y = ftanh(s);
            *lHn[nbuf][i] = y;
            st_cluster_f32(rHn[nbuf][i], y);
            if (A.outHi) {
                size_t gi = ((size_t)t*BATCH + batch0 + bOf[i])*HID + (int)rank*128 + jOf[i];
                __nv_bfloat16 h = __float2bfloat16(y);
                A.outHi[gi] = h;
                A.outLo[gi] = __float2bfloat16(y - __bfloat162float(h));
            }
            if (A.hFinal && t == T_STEPS-1)
                A.hFinal[(size_t)(batch0 + bOf[i])*HID + (int)rank*128 + jOf[i]] = y;
        }
        // R5 protocol: every thread arrives remote then local, then waits.
        mbar_arrive_remote_addr(rBar);
        mbar_arrive_local(barAddr);
        mbar_wait_cluster(barAddr, (uint32_t)(t & 1));
    }
    cluster_sync_();
}

// -------------------- split converters --------------------
__global__ void wsplit(const float* __restrict__ W, __nv_bfloat16* __restrict__ hi,
                       __nv_bfloat16* __restrict__ lo, int Nw, int Kw, int Kp)
{
    int i = blockIdx.x*blockDim.x + threadIdx.x;
    if (i >= 256*Kp) return;
    int r = i / Kp, c = i - r*Kp;
    float v = (r < Nw && c < Kw) ? W[r*Kw + c] : 0.f;
    __nv_bfloat16 h = __float2bfloat16(v);
    hi[i] = h;
    lo[i] = __float2bfloat16(v - __bfloat162float(h));
}

__global__ void xsplit(const float* __restrict__ src, __nv_bfloat16* __restrict__ hi,
                       __nv_bfloat16* __restrict__ lo)
{
    const size_t total = (size_t)MROWS*KP_IN;
    for (size_t i = (size_t)blockIdx.x*blockDim.x + threadIdx.x; i < total;
         i += (size_t)gridDim.x*blockDim.x) {
        size_t r = i / KP_IN;
        int c = (int)(i - r*KP_IN);
        float v = (c < IN_DIM) ? src[r*IN_DIM + c] : 0.f;
        __nv_bfloat16 h = __float2bfloat16(v);
        hi[i] = h;
        lo[i] = __float2bfloat16(v - __bfloat162float(h));
    }
}

__global__ void decsplit(const float* __restrict__ X, const float* __restrict__ Y,
                         __nv_bfloat16* __restrict__ hi, __nv_bfloat16* __restrict__ lo)
{
    const size_t total = (size_t)MROWS*KP_IN;
    for (size_t i = (size_t)blockIdx.x*blockDim.x + threadIdx.x; i < total;
         i += (size_t)gridDim.x*blockDim.x) {
        size_t r = i / KP_IN;
        int c = (int)(i - r*KP_IN);
        float v = 0.f;
        if (c < IN_DIM)
            v = (r < BATCH) ? X[((size_t)1023*BATCH + r)*IN_DIM + c]
                            : Y[(r - BATCH)*IN_DIM + c];
        __nv_bfloat16 h = __float2bfloat16(v);
        hi[i] = h;
        lo[i] = __float2bfloat16(v - __bfloat162float(h));
    }
}

// -------------------- log_softmax in place --------------------
__global__ void __launch_bounds__(256) logsoftmax_kernel(float* __restrict__ out, int rows) {
    int row = blockIdx.x*8 + (threadIdx.x >> 5);
    int lane = threadIdx.x & 31;
    if (row >= rows) return;
    float* p = out + (size_t)row*OUT_DIM;
    float v[5];
    float mx = -1e30f;
    #pragma unroll
    for (int i = 0; i < 5; i++) {
        int idx = lane + i*32;
        v[i] = (idx < OUT_DIM) ? p[idx] : -1e30f;
        mx = fmaxf(mx, v[i]);
    }
    #pragma unroll
    for (int o = 16; o > 0; o >>= 1)
        mx = fmaxf(mx, __shfl_xor_sync(0xffffffffu, mx, o));
    float s = 0.f;
    #pragma unroll
    for (int i = 0; i < 5; i++) {
        int idx = lane + i*32;
        if (idx < OUT_DIM) s += expf(v[i] - mx);
    }
    #pragma unroll
    for (int o = 16; o > 0; o >>= 1)
        s += __shfl_xor_sync(0xffffffffu, s, o);
    float lse = mx + logf(s);
    #pragma unroll
    for (int i = 0; i < 5; i++) {
        int idx = lane + i*32;
        if (idx < OUT_DIM) p[idx] = v[i] - lse;
    }
}

// -------------------- driver --------------------
extern "C" void kernel_launch(void* const* d_in, const int* in_sizes, int n_in,
                              void* d_out, int out_size) {
    const float* X     = (const float*)d_in[0];
    const float* Y     = (const float*)d_in[1];
    const float* eWih0 = (const float*)d_in[2];
    const float* eWhh0 = (const float*)d_in[3];
    const float* ebih0 = (const float*)d_in[4];
    const float* ebhh0 = (const float*)d_in[5];
    const float* eWih1 = (const float*)d_in[6];
    const float* eWhh1 = (const float*)d_in[7];
    const float* ebih1 = (const float*)d_in[8];
    const float* ebhh1 = (const float*)d_in[9];
    const float* dWih0 = (const float*)d_in[10];
    const float* dWhh0 = (const float*)d_in[11];
    const float* dbih0 = (const float*)d_in[12];
    const float* dbhh0 = (const float*)d_in[13];
    const float* dWih1 = (const float*)d_in[14];
    const float* dWhh1 = (const float*)d_in[15];
    const float* dbih1 = (const float*)d_in[16];
    const float* dbhh1 = (const float*)d_in[17];
    const float* lin_W = (const float*)d_in[18];
    const float* lin_b = (const float*)d_in[19];
    float* out = (float*)d_out;

    char* buf;
    float *hn0, *hn1;
    __nv_bfloat16 *Wh, *Wl;
    cudaGetSymbolAddress((void**)&buf, g_buf);
    cudaGetSymbolAddress((void**)&Wh,  g_Wh);
    cudaGetSymbolAddress((void**)&Wl,  g_Wl);
    cudaGetSymbolAddress((void**)&hn0, g_hn0);
    cudaGetSymbolAddress((void**)&hn1, g_hn1);

    float* Zenc = (float*)(buf);
    float* Zdec = (float*)(buf + ZBYTES);
    char*  r3   = buf + 2*ZBYTES;
    const size_t HBYTES = (size_t)MROWS*HID*2;
    const size_t XBYTES = (size_t)MROWS*KP_IN*2;
    __nv_bfloat16* Hhi = (__nv_bfloat16*)(r3);
    __nv_bfloat16* Hlo = (__nv_bfloat16*)(r3 + HBYTES);
    __nv_bfloat16* Xhi = (__nv_bfloat16*)(r3);
    __nv_bfloat16* Xlo = (__nv_bfloat16*)(r3 + XBYTES);
    __nv_bfloat16* Dhi = Xhi;
    __nv_bfloat16* Dlo = Xlo;

    cudaFuncSetAttribute((const void*)recur_kernel<4>,
                         cudaFuncAttributeMaxDynamicSharedMemorySize, RECUR_SMEM(4));
    cudaFuncSetAttribute((const void*)recur_kernel<8>,
                         cudaFuncAttributeMaxDynamicSharedMemorySize, RECUR_SMEM(8));
    cudaFuncSetAttribute((const void*)gemm_mma,
                         cudaFuncAttributeMaxDynamicSharedMemorySize, GM_SMEM);

    const int WSTRIDE = 256*256;
    const dim3 gG(MROWS/128, 2);

    wsplit<<<(256*KP_IN+255)/256, 256>>>(eWih0, Wh+0*WSTRIDE, Wl+0*WSTRIDE, HID, IN_DIM, KP_IN);
    wsplit<<<(256*KP_IN+255)/256, 256>>>(dWih0, Wh+1*WSTRIDE, Wl+1*WSTRIDE, HID, IN_DIM, KP_IN);
    wsplit<<<(256*256+255)/256, 256>>>(eWih1, Wh+2*WSTRIDE, Wl+2*WSTRIDE, HID, HID, 256);
    wsplit<<<(256*256+255)/256, 256>>>(dWih1, Wh+3*WSTRIDE, Wl+3*WSTRIDE, HID, HID, 256);
    wsplit<<<(256*256+255)/256, 256>>>(lin_W, Wh+4*WSTRIDE, Wl+4*WSTRIDE, OUT_DIM, HID, 256);

    xsplit<<<4096, 256>>>(X, Xhi, Xlo);
    gemm_mma<<<gG, 256, GM_SMEM>>>(Xhi, Xlo, Wh+0*WSTRIDE, Wl+0*WSTRIDE,
                                   ebih0, ebhh0, Zenc, 256, KP_IN);
    decsplit<<<4096, 256>>>(X, Y, Dhi, Dlo);
    gemm_mma<<<gG, 256, GM_SMEM>>>(Dhi, Dlo, Wh+1*WSTRIDE, Wl+1*WSTRIDE,
                                   dbih0, dbhh0, Zdec, 256, KP_IN);
    {
        RArgs a; a.Z = Zenc; a.outHi = Hhi; a.outLo = Hlo; a.W = eWhh0; a.hInit = nullptr; a.hFinal = hn0;
        recur_kernel<4><<<128, 256, RECUR_SMEM(4)>>>(a, a, 64);
    }
    gemm_mma<<<gG, 256, GM_SMEM>>>(Hhi, Hlo, Wh+2*WSTRIDE, Wl+2*WSTRIDE,
                                   ebih1, ebhh1, Zenc, 256, 256);
    {
        RArgs a0; a0.Z = Zenc; a0.outHi = nullptr; a0.outLo = nullptr; a0.W = eWhh1; a0.hInit = nullptr; a0.hFinal = hn1;
        RArgs a1; a1.Z = Zdec; a1.outHi = Hhi;     a1.outLo = Hlo;     a1.W = dWhh0; a1.hInit = hn0;     a1.hFinal = nullptr;
        recur_kernel<8><<<128, 256, RECUR_SMEM(8)>>>(a0, a1, 32);
    }
    gemm_mma<<<gG, 256, GM_SMEM>>>(Hhi, Hlo, Wh+3*WSTRIDE, Wl+3*WSTRIDE,
                                   dbih1, dbhh1, Zdec, 256, 256);
    {
        RArgs a; a.Z = Zdec; a.outHi = Hhi; a.outLo = Hlo; a.W = dWhh1; a.hInit = hn1; a.hFinal = nullptr;
        recur_kernel<4><<<128, 256, RECUR_SMEM(4)>>>(a, a, 64);
    }
    gemm_mma<<<gG, 256, GM_SMEM>>>(Hhi, Hlo, Wh+4*WSTRIDE, Wl+4*WSTRIDE,
                                   lin_b, nullptr, out, OUT_DIM, 256);
    logsoftmax_kernel<<<(MROWS + 7)/8, 256>>>(out, MROWS);
}